// round 1
// baseline (speedup 1.0000x reference)
#include <cuda_runtime.h>

#define M_ROWS 8192
#define EMB 1024
#define FFN 4096
#define NQ 32

// ---------------- scratch (device globals; no allocations) ----------------
__device__ __align__(16) float g_attnv[M_ROWS * NQ];        // attention out (pre-combine)
__device__ __align__(16) float g_comb [M_ROWS * EMB];       // attnv @ w_combine^T
__device__ __align__(16) float g_x1   [M_ROWS * EMB];       // after LN1
__device__ __align__(16) float g_qf   [M_ROWS * NQ];        // ffn quantum features
__device__ __align__(16) float g_h    [(size_t)M_ROWS * FFN]; // relu(qf @ w1^T)
__device__ __align__(16) float g_ffn  [M_ROWS * EMB];       // h @ w2^T

// ---------------- helpers ----------------
__device__ __forceinline__ unsigned long long ffma2(unsigned long long a,
                                                    unsigned long long b,
                                                    unsigned long long c) {
    unsigned long long d;
    asm("fma.rn.f32x2 %0, %1, %2, %3;" : "=l"(d) : "l"(a), "l"(b), "l"(c));
    return d;
}
__device__ __forceinline__ unsigned long long dup2(float v) {
    unsigned int u = __float_as_uint(v);
    return ((unsigned long long)u << 32) | (unsigned long long)u;
}
__device__ __forceinline__ float f2lo(unsigned long long v) { return __uint_as_float((unsigned int)v); }
__device__ __forceinline__ float f2hi(unsigned long long v) { return __uint_as_float((unsigned int)(v >> 32)); }

// block-wide sum of (s, q) over 256 threads; result broadcast to all threads
__device__ __forceinline__ void blockReduce2(float& s, float& q) {
    __shared__ float buf[16];
    #pragma unroll
    for (int o = 16; o > 0; o >>= 1) {
        s += __shfl_xor_sync(0xffffffffu, s, o);
        q += __shfl_xor_sync(0xffffffffu, q, o);
    }
    int w = threadIdx.x >> 5, l = threadIdx.x & 31;
    if (l == 0) { buf[w] = s; buf[8 + w] = q; }
    __syncthreads();
    if (threadIdx.x < 32) {
        float ss = (l < 8) ? buf[l] : 0.0f;
        float qq = (l < 8) ? buf[8 + l] : 0.0f;
        #pragma unroll
        for (int o = 4; o > 0; o >>= 1) {
            ss += __shfl_xor_sync(0xffffffffu, ss, o);
            qq += __shfl_xor_sync(0xffffffffu, qq, o);
        }
        if (l == 0) { buf[0] = ss; buf[8] = qq; }
    }
    __syncthreads();
    s = buf[0];
    q = buf[8];
}

// ---------------- K2: quantum attention per (b, h) ----------------
// q = k = v = cos(theta) * cos(x[..., h*2 .. h*2+1]); dk = 2, scale 1/sqrt(2)
__global__ __launch_bounds__(256) void attn_kernel(const float* __restrict__ x,
                                                   const float* __restrict__ theta) {
    __shared__ float2 q2[1024];
    int bh = blockIdx.x;
    int b = bh >> 4, h = bh & 15;
    float c0 = cosf(theta[h * 2]);
    float c1 = cosf(theta[h * 2 + 1]);
    const float* xb = x + (size_t)b * 1024 * 1024 + h * 2;
    for (int i = threadIdx.x; i < 1024; i += 256) {
        float2 v = *(const float2*)(xb + (size_t)i * 1024);
        q2[i] = make_float2(c0 * cosf(v.x), c1 * cosf(v.y));
    }
    __syncthreads();
    int s = blockIdx.y * 256 + threadIdx.x;
    float2 qs = q2[s];
    const float inv_sqrt2 = 0.70710678118654752f;
    float sxp = qs.x * inv_sqrt2, syp = qs.y * inv_sqrt2;
    float sum = 0.0f, ax = 0.0f, ay = 0.0f;
    #pragma unroll 4
    for (int t = 0; t < 1024; t++) {
        float2 qt = q2[t];
        float e = __expf(sxp * qt.x + syp * qt.y);
        sum += e;
        ax += e * qt.x;
        ay += e * qt.y;
    }
    float inv = 1.0f / sum;
    size_t o = ((size_t)b * 1024 + s) * NQ + h * 2;
    g_attnv[o]     = ax * inv;
    g_attnv[o + 1] = ay * inv;
}

// ---------------- small-K GEMM (K=32): C[M,N] = A[M,32] @ B[N,32]^T ----------------
// mode 0: A=g_attnv, C=g_comb (combine);  mode 1: A=g_qf, C=g_h (+relu)
__global__ __launch_bounds__(256, 2) void smallk_gemm(const float* __restrict__ Bmat,
                                                      int N, int relu, int mode) {
    __shared__ __align__(16) float As[32 * 132];
    __shared__ __align__(16) float Bs[32 * 132];
    const float* A = mode ? g_qf : g_attnv;
    float* C = mode ? g_h : g_comb;
    int tid = threadIdx.x;
    int m0 = blockIdx.y * 128, n0 = blockIdx.x * 128;
    const float4* A4 = (const float4*)(A + (size_t)m0 * 32);
    const float4* B4 = (const float4*)(Bmat + (size_t)n0 * 32);
    #pragma unroll
    for (int i = 0; i < 4; i++) {
        int f = i * 256 + tid;
        int r = f >> 3, c4 = f & 7;
        float4 va = A4[r * 8 + c4];
        As[(c4 * 4 + 0) * 132 + r] = va.x;
        As[(c4 * 4 + 1) * 132 + r] = va.y;
        As[(c4 * 4 + 2) * 132 + r] = va.z;
        As[(c4 * 4 + 3) * 132 + r] = va.w;
        float4 vb = B4[r * 8 + c4];
        Bs[(c4 * 4 + 0) * 132 + r] = vb.x;
        Bs[(c4 * 4 + 1) * 132 + r] = vb.y;
        Bs[(c4 * 4 + 2) * 132 + r] = vb.z;
        Bs[(c4 * 4 + 3) * 132 + r] = vb.w;
    }
    __syncthreads();
    int tx = tid & 15, ty = tid >> 4;
    int tx4 = tx * 4, ty4 = ty * 4;
    float acc[8][8];
    #pragma unroll
    for (int i = 0; i < 8; i++)
        #pragma unroll
        for (int j = 0; j < 8; j++) acc[i][j] = 0.0f;

    #pragma unroll
    for (int k = 0; k < 32; k++) {
        float4 a0 = *(const float4*)&As[k * 132 + ty4];
        float4 a1 = *(const float4*)&As[k * 132 + 64 + ty4];
        float4 b0 = *(const float4*)&Bs[k * 132 + tx4];
        float4 b1 = *(const float4*)&Bs[k * 132 + 64 + tx4];
        float a[8] = {a0.x, a0.y, a0.z, a0.w, a1.x, a1.y, a1.z, a1.w};
        float b[8] = {b0.x, b0.y, b0.z, b0.w, b1.x, b1.y, b1.z, b1.w};
        #pragma unroll
        for (int i = 0; i < 8; i++)
            #pragma unroll
            for (int j = 0; j < 8; j++) acc[i][j] += a[i] * b[j];
    }
    #pragma unroll
    for (int i = 0; i < 8; i++) {
        int m = m0 + ((i < 4) ? (ty4 + i) : (64 + ty4 + i - 4));
        float* Crow = C + (size_t)m * N + n0;
        float4 o0 = make_float4(acc[i][0], acc[i][1], acc[i][2], acc[i][3]);
        float4 o1 = make_float4(acc[i][4], acc[i][5], acc[i][6], acc[i][7]);
        if (relu) {
            o0.x = fmaxf(o0.x, 0.0f); o0.y = fmaxf(o0.y, 0.0f);
            o0.z = fmaxf(o0.z, 0.0f); o0.w = fmaxf(o0.w, 0.0f);
            o1.x = fmaxf(o1.x, 0.0f); o1.y = fmaxf(o1.y, 0.0f);
            o1.z = fmaxf(o1.z, 0.0f); o1.w = fmaxf(o1.w, 0.0f);
        }
        *(float4*)&Crow[tx4]      = o0;
        *(float4*)&Crow[64 + tx4] = o1;
    }
}

// ---------------- LN1 + qf ----------------
__global__ __launch_bounds__(256) void ln1_kernel(const float* __restrict__ x,
                                                  const float* __restrict__ g1,
                                                  const float* __restrict__ b1,
                                                  const float* __restrict__ thf) {
    int row = blockIdx.x;
    const float* xr = x + (size_t)row * EMB;
    const float* cr = g_comb + (size_t)row * EMB;
    float v[4];
    float s = 0.0f, q = 0.0f;
    #pragma unroll
    for (int i = 0; i < 4; i++) {
        int e = i * 256 + threadIdx.x;
        v[i] = xr[e] + cr[e];
        s += v[i];
        q += v[i] * v[i];
    }
    blockReduce2(s, q);
    float mu = s * (1.0f / 1024.0f);
    float var = q * (1.0f / 1024.0f) - mu * mu;
    float rstd = rsqrtf(var + 1e-5f);
    #pragma unroll
    for (int i = 0; i < 4; i++) {
        int e = i * 256 + threadIdx.x;
        float y = (v[i] - mu) * rstd * g1[e] + b1[e];
        g_x1[(size_t)row * EMB + e] = y;
        if (i == 0 && threadIdx.x < NQ)
            g_qf[(size_t)row * NQ + threadIdx.x] = cosf(thf[threadIdx.x]) * cosf(y);
    }
}

// ---------------- big GEMM: g_ffn[8192,1024] = g_h[8192,4096] @ W2[1024,4096]^T ----------------
// f32x2 (FFMA2) microkernel; A tile stored pre-duplicated in smem as (v,v) u64 pairs.
__global__ __launch_bounds__(256, 2) void big_gemm(const float* __restrict__ W2) {
    __shared__ __align__(16) unsigned long long As2[16 * 130];
    __shared__ __align__(16) float Bs[16 * 132];
    int tid = threadIdx.x;
    int n0 = blockIdx.x * 128, m0 = blockIdx.y * 128;
    int tx = tid & 15, ty = tid >> 4;
    int tx4 = tx * 4, ty4 = ty * 4;
    const float4* A4 = (const float4*)g_h;
    const float4* B4 = (const float4*)W2;

    unsigned long long c2[8][4];
    #pragma unroll
    for (int i = 0; i < 8; i++)
        #pragma unroll
        for (int j = 0; j < 4; j++) c2[i][j] = 0ull;

    float4 pa[2], pb[2];
    // prefetch tile 0
    #pragma unroll
    for (int i = 0; i < 2; i++) {
        int f = tid + i * 256;
        int r = f >> 2, c4 = f & 3;
        pa[i] = A4[(size_t)(m0 + r) * 1024 + c4];
        pb[i] = B4[(size_t)(n0 + r) * 1024 + c4];
    }

    for (int kt = 0; kt < 256; ++kt) {
        // stage regs -> smem (A duplicated for f32x2)
        #pragma unroll
        for (int i = 0; i < 2; i++) {
            int f = tid + i * 256;
            int r = f >> 2, c4 = f & 3;
            float4 va = pa[i];
            As2[(c4 * 4 + 0) * 130 + r] = dup2(va.x);
            As2[(c4 * 4 + 1) * 130 + r] = dup2(va.y);
            As2[(c4 * 4 + 2) * 130 + r] = dup2(va.z);
            As2[(c4 * 4 + 3) * 130 + r] = dup2(va.w);
            float4 vb = pb[i];
            Bs[(c4 * 4 + 0) * 132 + r] = vb.x;
            Bs[(c4 * 4 + 1) * 132 + r] = vb.y;
            Bs[(c4 * 4 + 2) * 132 + r] = vb.z;
            Bs[(c4 * 4 + 3) * 132 + r] = vb.w;
        }
        __syncthreads();
        if (kt + 1 < 256) {
            int kq = (kt + 1) * 4;
            #pragma unroll
            for (int i = 0; i < 2; i++) {
                int f = tid + i * 256;
                int r = f >> 2, c4 = f & 3;
                pa[i] = A4[(size_t)(m0 + r) * 1024 + kq + c4];
                pb[i] = B4[(size_t)(n0 + r) * 1024 + kq + c4];
            }
        }
        #pragma unroll
        for (int k = 0; k < 16; k++) {
            ulonglong2 a01 = *(const ulonglong2*)&As2[k * 130 + ty4];
            ulonglong2 a23 = *(const ulonglong2*)&As2[k * 130 + ty4 + 2];
            ulonglong2 a45 = *(const ulonglong2*)&As2[k * 130 + 64 + ty4];
            ulonglong2 a67 = *(const ulonglong2*)&As2[k * 130 + 64 + ty4 + 2];
            ulonglong2 bl = *(const ulonglong2*)&Bs[k * 132 + tx4];
            ulonglong2 bh = *(const ulonglong2*)&Bs[k * 132 + 64 + tx4];
            unsigned long long au[8] = {a01.x, a01.y, a23.x, a23.y, a45.x, a45.y, a67.x, a67.y};
            unsigned long long bu[4] = {bl.x, bl.y, bh.x, bh.y};
            #pragma unroll
            for (int i = 0; i < 8; i++)
                #pragma unroll
                for (int j = 0; j < 4; j++) c2[i][j] = ffma2(au[i], bu[j], c2[i][j]);
        }
        __syncthreads();
    }
    #pragma unroll
    for (int i = 0; i < 8; i++) {
        int m = m0 + ((i < 4) ? (ty4 + i) : (64 + ty4 + i - 4));
        float* Crow = g_ffn + (size_t)m * EMB + n0;
        *(float4*)&Crow[tx4] =
            make_float4(f2lo(c2[i][0]), f2hi(c2[i][0]), f2lo(c2[i][1]), f2hi(c2[i][1]));
        *(float4*)&Crow[64 + tx4] =
            make_float4(f2lo(c2[i][2]), f2hi(c2[i][2]), f2lo(c2[i][3]), f2hi(c2[i][3]));
    }
}

// ---------------- LN2 -> out ----------------
__global__ __launch_bounds__(256) void ln2_kernel(const float* __restrict__ g2,
                                                  const float* __restrict__ b2,
                                                  float* __restrict__ out) {
    int row = blockIdx.x;
    const float* xr = g_x1 + (size_t)row * EMB;
    const float* fr = g_ffn + (size_t)row * EMB;
    float v[4];
    float s = 0.0f, q = 0.0f;
    #pragma unroll
    for (int i = 0; i < 4; i++) {
        int e = i * 256 + threadIdx.x;
        v[i] = xr[e] + fr[e];
        s += v[i];
        q += v[i] * v[i];
    }
    blockReduce2(s, q);
    float mu = s * (1.0f / 1024.0f);
    float var = q * (1.0f / 1024.0f) - mu * mu;
    float rstd = rsqrtf(var + 1e-5f);
    #pragma unroll
    for (int i = 0; i < 4; i++) {
        int e = i * 256 + threadIdx.x;
        out[(size_t)row * EMB + e] = (v[i] - mu) * rstd * g2[e] + b2[e];
    }
}

// ---------------- launch ----------------
extern "C" void kernel_launch(void* const* d_in, const int* in_sizes, int n_in,
                              void* d_out, int out_size) {
    const float* x    = (const float*)d_in[0];
    const float* th_a = (const float*)d_in[1];
    const float* th_f = (const float*)d_in[2];
    const float* w_c  = (const float*)d_in[3];
    const float* w1   = (const float*)d_in[4];
    const float* w2   = (const float*)d_in[5];
    const float* g1   = (const float*)d_in[6];
    const float* b1   = (const float*)d_in[7];
    const float* g2   = (const float*)d_in[8];
    const float* b2   = (const float*)d_in[9];
    float* out = (float*)d_out;

    attn_kernel<<<dim3(128, 4), 256>>>(x, th_a);
    smallk_gemm<<<dim3(EMB / 128, M_ROWS / 128), 256>>>(w_c, EMB, 0, 0);
    ln1_kernel<<<M_ROWS, 256>>>(x, g1, b1, th_f);
    smallk_gemm<<<dim3(FFN / 128, M_ROWS / 128), 256>>>(w1, FFN, 1, 1);
    big_gemm<<<dim3(EMB / 128, M_ROWS / 128), 256>>>(w2);
    ln2_kernel<<<M_ROWS, 256>>>(g2, b2, out);
}

// round 3
// speedup vs baseline: 2.8339x; 2.8339x over previous
#include <cuda_runtime.h>
#include <cstdint>

#define M_ROWS 8192
#define EMB 1024
#define FFN 4096
#define NQ 32

// ---------------- scratch (device globals; no allocations) ----------------
__device__ __align__(16) float g_attnv[M_ROWS * NQ];
__device__ __align__(16) float g_comb [M_ROWS * EMB];
__device__ __align__(16) float g_x1   [M_ROWS * EMB];
__device__ __align__(16) float g_qf   [M_ROWS * NQ];
__device__ __align__(16) float g_ffn  [M_ROWS * EMB];
__device__ __align__(16) float g_h    [(size_t)M_ROWS * FFN];  // tf32-rounded fp32
__device__ __align__(16) float g_w2t  [(size_t)EMB * FFN];     // tf32-rounded fp32

// ---------------- helpers ----------------
__device__ __forceinline__ float tf32r(float x) {
    uint32_t u;
    asm("cvt.rna.tf32.f32 %0, %1;" : "=r"(u) : "f"(x));
    return __uint_as_float(u);
}
__device__ __forceinline__ uint32_t smem_u32(const void* p) {
    uint32_t a;
    asm("{ .reg .u64 t; cvta.to.shared.u64 t, %1; cvt.u32.u64 %0, t; }" : "=r"(a) : "l"(p));
    return a;
}
__device__ __forceinline__ void cp16(uint32_t dst, const void* src) {
    asm volatile("cp.async.cg.shared.global [%0], [%1], 16;" :: "r"(dst), "l"(src));
}
__device__ __forceinline__ void cp_commit() { asm volatile("cp.async.commit_group;" ::: "memory"); }
template <int N> __device__ __forceinline__ void cp_wait() {
    asm volatile("cp.async.wait_group %0;" :: "n"(N) : "memory");
}
__device__ __forceinline__ void mma_tf32(float* c, const uint32_t* a, const uint32_t* b) {
    asm volatile(
        "mma.sync.aligned.m16n8k8.row.col.f32.tf32.tf32.f32 "
        "{%0,%1,%2,%3}, {%4,%5,%6,%7}, {%8,%9}, {%0,%1,%2,%3};"
        : "+f"(c[0]), "+f"(c[1]), "+f"(c[2]), "+f"(c[3])
        : "r"(a[0]), "r"(a[1]), "r"(a[2]), "r"(a[3]), "r"(b[0]), "r"(b[1]));
}

// block-wide sum of (s, q) over 256 threads; result broadcast
__device__ __forceinline__ void blockReduce2(float& s, float& q) {
    __shared__ float buf[16];
    #pragma unroll
    for (int o = 16; o > 0; o >>= 1) {
        s += __shfl_xor_sync(0xffffffffu, s, o);
        q += __shfl_xor_sync(0xffffffffu, q, o);
    }
    int w = threadIdx.x >> 5, l = threadIdx.x & 31;
    if (l == 0) { buf[w] = s; buf[8 + w] = q; }
    __syncthreads();
    if (threadIdx.x < 32) {
        float ss = (l < 8) ? buf[l] : 0.0f;
        float qq = (l < 8) ? buf[8 + l] : 0.0f;
        #pragma unroll
        for (int o = 4; o > 0; o >>= 1) {
            ss += __shfl_xor_sync(0xffffffffu, ss, o);
            qq += __shfl_xor_sync(0xffffffffu, qq, o);
        }
        if (l == 0) { buf[0] = ss; buf[8] = qq; }
    }
    __syncthreads();
    s = buf[0];
    q = buf[8];
}

// ---------------- attention ----------------
__global__ __launch_bounds__(256) void attn_kernel(const float* __restrict__ x,
                                                   const float* __restrict__ theta) {
    __shared__ float2 q2[1024];
    int bh = blockIdx.x;
    int b = bh >> 4, h = bh & 15;
    float c0 = cosf(theta[h * 2]);
    float c1 = cosf(theta[h * 2 + 1]);
    const float* xb = x + (size_t)b * 1024 * 1024 + h * 2;
    for (int i = threadIdx.x; i < 1024; i += 256) {
        float2 v = *(const float2*)(xb + (size_t)i * 1024);
        q2[i] = make_float2(c0 * cosf(v.x), c1 * cosf(v.y));
    }
    __syncthreads();
    int s = blockIdx.y * 256 + threadIdx.x;
    float2 qs = q2[s];
    const float inv_sqrt2 = 0.70710678118654752f;
    float sxp = qs.x * inv_sqrt2, syp = qs.y * inv_sqrt2;
    float sum = 0.0f, ax = 0.0f, ay = 0.0f;
    #pragma unroll 4
    for (int t = 0; t < 1024; t++) {
        float2 qt = q2[t];
        float e = __expf(sxp * qt.x + syp * qt.y);
        sum += e;
        ax += e * qt.x;
        ay += e * qt.y;
    }
    float inv = 1.0f / sum;
    size_t o = ((size_t)b * 1024 + s) * NQ + h * 2;
    g_attnv[o]     = ax * inv;
    g_attnv[o + 1] = ay * inv;
}

// ---------------- small-K GEMM (K=32) ----------------
// mode 0: g_comb = g_attnv @ Bmat^T (fp32)
// mode 1: g_h = tf32_round(relu(g_qf @ Bmat^T))
__global__ __launch_bounds__(256, 2) void smallk_gemm(const float* __restrict__ Bmat,
                                                      int N, int relu, int mode) {
    __shared__ __align__(16) float As[32 * 132];
    __shared__ __align__(16) float Bs[32 * 132];
    const float* A = mode ? g_qf : g_attnv;
    float* C = mode ? g_h : g_comb;
    int tid = threadIdx.x;
    int m0 = blockIdx.y * 128, n0 = blockIdx.x * 128;
    const float4* A4 = (const float4*)(A + (size_t)m0 * 32);
    const float4* B4 = (const float4*)(Bmat + (size_t)n0 * 32);
    #pragma unroll
    for (int i = 0; i < 4; i++) {
        int f = i * 256 + tid;
        int r = f >> 3, c4 = f & 7;
        float4 va = A4[r * 8 + c4];
        As[(c4 * 4 + 0) * 132 + r] = va.x;
        As[(c4 * 4 + 1) * 132 + r] = va.y;
        As[(c4 * 4 + 2) * 132 + r] = va.z;
        As[(c4 * 4 + 3) * 132 + r] = va.w;
        float4 vb = B4[r * 8 + c4];
        Bs[(c4 * 4 + 0) * 132 + r] = vb.x;
        Bs[(c4 * 4 + 1) * 132 + r] = vb.y;
        Bs[(c4 * 4 + 2) * 132 + r] = vb.z;
        Bs[(c4 * 4 + 3) * 132 + r] = vb.w;
    }
    __syncthreads();
    int tx = tid & 15, ty = tid >> 4;
    int tx4 = tx * 4, ty4 = ty * 4;
    float acc[8][8];
    #pragma unroll
    for (int i = 0; i < 8; i++)
        #pragma unroll
        for (int j = 0; j < 8; j++) acc[i][j] = 0.0f;

    #pragma unroll
    for (int k = 0; k < 32; k++) {
        float4 a0 = *(const float4*)&As[k * 132 + ty4];
        float4 a1 = *(const float4*)&As[k * 132 + 64 + ty4];
        float4 b0 = *(const float4*)&Bs[k * 132 + tx4];
        float4 b1 = *(const float4*)&Bs[k * 132 + 64 + tx4];
        float a[8] = {a0.x, a0.y, a0.z, a0.w, a1.x, a1.y, a1.z, a1.w};
        float b[8] = {b0.x, b0.y, b0.z, b0.w, b1.x, b1.y, b1.z, b1.w};
        #pragma unroll
        for (int i = 0; i < 8; i++)
            #pragma unroll
            for (int j = 0; j < 8; j++) acc[i][j] += a[i] * b[j];
    }
    #pragma unroll
    for (int i = 0; i < 8; i++) {
        int m = m0 + ((i < 4) ? (ty4 + i) : (64 + ty4 + i - 4));
        float* Crow = C + (size_t)m * N + n0;
        float4 o0 = make_float4(acc[i][0], acc[i][1], acc[i][2], acc[i][3]);
        float4 o1 = make_float4(acc[i][4], acc[i][5], acc[i][6], acc[i][7]);
        if (relu) {
            o0.x = tf32r(fmaxf(o0.x, 0.0f)); o0.y = tf32r(fmaxf(o0.y, 0.0f));
            o0.z = tf32r(fmaxf(o0.z, 0.0f)); o0.w = tf32r(fmaxf(o0.w, 0.0f));
            o1.x = tf32r(fmaxf(o1.x, 0.0f)); o1.y = tf32r(fmaxf(o1.y, 0.0f));
            o1.z = tf32r(fmaxf(o1.z, 0.0f)); o1.w = tf32r(fmaxf(o1.w, 0.0f));
        }
        *(float4*)&Crow[tx4]      = o0;
        *(float4*)&Crow[64 + tx4] = o1;
    }
}

// ---------------- W2 -> tf32-rounded copy ----------------
__global__ __launch_bounds__(256) void conv_w2_kernel(const float* __restrict__ w2) {
    size_t i = (size_t)blockIdx.x * 256 + threadIdx.x;   // over EMB*FFN/4 float4s
    float4 v = ((const float4*)w2)[i];
    v.x = tf32r(v.x); v.y = tf32r(v.y); v.z = tf32r(v.z); v.w = tf32r(v.w);
    ((float4*)g_w2t)[i] = v;
}

// ---------------- LN1 + qf ----------------
__global__ __launch_bounds__(256) void ln1_kernel(const float* __restrict__ x,
                                                  const float* __restrict__ g1,
                                                  const float* __restrict__ b1,
                                                  const float* __restrict__ thf) {
    int row = blockIdx.x;
    const float* xr = x + (size_t)row * EMB;
    const float* cr = g_comb + (size_t)row * EMB;
    float v[4];
    float s = 0.0f, q = 0.0f;
    #pragma unroll
    for (int i = 0; i < 4; i++) {
        int e = i * 256 + threadIdx.x;
        v[i] = xr[e] + cr[e];
        s += v[i];
        q += v[i] * v[i];
    }
    blockReduce2(s, q);
    float mu = s * (1.0f / 1024.0f);
    float var = q * (1.0f / 1024.0f) - mu * mu;
    float rstd = rsqrtf(var + 1e-5f);
    #pragma unroll
    for (int i = 0; i < 4; i++) {
        int e = i * 256 + threadIdx.x;
        float y = (v[i] - mu) * rstd * g1[e] + b1[e];
        g_x1[(size_t)row * EMB + e] = y;
        if (i == 0 && threadIdx.x < NQ)
            g_qf[(size_t)row * NQ + threadIdx.x] = cosf(thf[threadIdx.x]) * cosf(y);
    }
}

// ---------------- big GEMM: mma.sync tf32 ----------------
// g_ffn[8192,1024] = g_h[8192,4096] @ g_w2t[1024,4096]^T
// CTA tile 128x128, 8 warps (2 in M x 4 in N), warp tile 64x32, K-chunk 32.
static constexpr int BK = 32;
static constexpr int NCH = FFN / BK;                 // 128
static constexpr int LDSR = 36;                      // padded row stride (floats)
static constexpr int ATILE_B = 128 * LDSR * 4;       // 18432 bytes
static constexpr int BUF_B = 2 * ATILE_B;            // A + B per buffer
static constexpr int BG_SMEM = 2 * BUF_B;            // 73728 bytes

__global__ __launch_bounds__(256, 2) void big_gemm_tf32() {
    extern __shared__ __align__(16) float smem[];
    const uint32_t sbase = smem_u32(smem);
    const int tid = threadIdx.x;
    const int wid = tid >> 5, lane = tid & 31;
    const int g = lane >> 2, t = lane & 3;
    const int wm = (wid >> 2) * 64;                  // warp M offset (0/64)
    const int wn = (wid & 3) * 32;                   // warp N offset (0..96)
    const int m0 = blockIdx.y * 128;
    const int n0 = blockIdx.x * 128;

    float c[16][4];
    #pragma unroll
    for (int i = 0; i < 16; i++)
        #pragma unroll
        for (int j = 0; j < 4; j++) c[i][j] = 0.0f;

    auto load_chunk = [&](int ch, int b) {
        uint32_t abase = sbase + (uint32_t)b * BUF_B;
        uint32_t bbase = abase + ATILE_B;
        const float* ag = g_h   + (size_t)m0 * FFN + ch * BK;
        const float* bg = g_w2t + (size_t)n0 * FFN + ch * BK;
        #pragma unroll
        for (int it = 0; it < 4; it++) {
            int sgm = it * 256 + tid;
            int r = sgm >> 3, c4 = sgm & 7;
            uint32_t so = (uint32_t)(r * LDSR + c4 * 4) * 4;
            cp16(abase + so, ag + (size_t)r * FFN + c4 * 4);
            cp16(bbase + so, bg + (size_t)r * FFN + c4 * 4);
        }
        cp_commit();
    };

    load_chunk(0, 0);
    for (int i = 0; i < NCH; i++) {
        int b = i & 1;
        if (i + 1 < NCH) {
            load_chunk(i + 1, b ^ 1);
            cp_wait<1>();
        } else {
            cp_wait<0>();
        }
        __syncthreads();
        const float* As = smem + (size_t)b * (BUF_B / 4);
        const float* Bs = As + ATILE_B / 4;
        #pragma unroll
        for (int ks = 0; ks < 4; ks++) {
            int tk = ks * 8;
            uint32_t af[4][4], bf[4][2];
            #pragma unroll
            for (int mf = 0; mf < 4; mf++) {
                const float* ap = As + (wm + mf * 16 + g) * LDSR + tk + t;
                af[mf][0] = __float_as_uint(ap[0]);
                af[mf][1] = __float_as_uint(ap[8 * LDSR]);
                af[mf][2] = __float_as_uint(ap[4]);
                af[mf][3] = __float_as_uint(ap[8 * LDSR + 4]);
            }
            #pragma unroll
            for (int nf = 0; nf < 4; nf++) {
                const float* bp = Bs + (wn + nf * 8 + g) * LDSR + tk + t;
                bf[nf][0] = __float_as_uint(bp[0]);
                bf[nf][1] = __float_as_uint(bp[4]);
            }
            #pragma unroll
            for (int mf = 0; mf < 4; mf++)
                #pragma unroll
                for (int nf = 0; nf < 4; nf++)
                    mma_tf32(c[mf * 4 + nf], af[mf], bf[nf]);
        }
        __syncthreads();
    }

    // epilogue
    #pragma unroll
    for (int mf = 0; mf < 4; mf++) {
        int row0 = m0 + wm + mf * 16 + g;
        #pragma unroll
        for (int nf = 0; nf < 4; nf++) {
            int col = n0 + wn + nf * 8 + 2 * t;
            float* p0 = g_ffn + (size_t)row0 * EMB + col;
            float* p1 = g_ffn + (size_t)(row0 + 8) * EMB + col;
            *(float2*)p0 = make_float2(c[mf * 4 + nf][0], c[mf * 4 + nf][1]);
            *(float2*)p1 = make_float2(c[mf * 4 + nf][2], c[mf * 4 + nf][3]);
        }
    }
}

// ---------------- LN2 -> out ----------------
__global__ __launch_bounds__(256) void ln2_kernel(const float* __restrict__ g2,
                                                  const float* __restrict__ b2,
                                                  float* __restrict__ out) {
    int row = blockIdx.x;
    const float* xr = g_x1 + (size_t)row * EMB;
    const float* fr = g_ffn + (size_t)row * EMB;
    float v[4];
    float s = 0.0f, q = 0.0f;
    #pragma unroll
    for (int i = 0; i < 4; i++) {
        int e = i * 256 + threadIdx.x;
        v[i] = xr[e] + fr[e];
        s += v[i];
        q += v[i] * v[i];
    }
    blockReduce2(s, q);
    float mu = s * (1.0f / 1024.0f);
    float var = q * (1.0f / 1024.0f) - mu * mu;
    float rstd = rsqrtf(var + 1e-5f);
    #pragma unroll
    for (int i = 0; i < 4; i++) {
        int e = i * 256 + threadIdx.x;
        out[(size_t)row * EMB + e] = (v[i] - mu) * rstd * g2[e] + b2[e];
    }
}

// ---------------- launch ----------------
extern "C" void kernel_launch(void* const* d_in, const int* in_sizes, int n_in,
                              void* d_out, int out_size) {
    const float* x    = (const float*)d_in[0];
    const float* th_a = (const float*)d_in[1];
    const float* th_f = (const float*)d_in[2];
    const float* w_c  = (const float*)d_in[3];
    const float* w1   = (const float*)d_in[4];
    const float* w2   = (const float*)d_in[5];
    const float* g1   = (const float*)d_in[6];
    const float* b1   = (const float*)d_in[7];
    const float* g2   = (const float*)d_in[8];
    const float* b2   = (const float*)d_in[9];
    float* out = (float*)d_out;

    static bool attr_set = false;
    if (!attr_set) {
        cudaFuncSetAttribute(big_gemm_tf32, cudaFuncAttributeMaxDynamicSharedMemorySize, BG_SMEM);
        attr_set = true;
    }

    conv_w2_kernel<<<(EMB * FFN / 4) / 256, 256>>>(w2);
    attn_kernel<<<dim3(128, 4), 256>>>(x, th_a);
    smallk_gemm<<<dim3(EMB / 128, M_ROWS / 128), 256>>>(w_c, EMB, 0, 0);
    ln1_kernel<<<M_ROWS, 256>>>(x, g1, b1, th_f);
    smallk_gemm<<<dim3(FFN / 128, M_ROWS / 128), 256>>>(w1, FFN, 1, 1);
    big_gemm_tf32<<<dim3(EMB / 128, M_ROWS / 128), 256, BG_SMEM>>>();
    ln2_kernel<<<M_ROWS, 256>>>(g2, b2, out);
}

// round 4
// speedup vs baseline: 4.7688x; 1.6828x over previous
#include <cuda_runtime.h>
#include <cuda_fp16.h>
#include <cstdint>

#define M_ROWS 8192
#define EMB 1024
#define FFN 4096
#define NQ 32

// ---------------- scratch (device globals; no allocations) ----------------
__device__ __align__(16) __half g_attnv[M_ROWS * NQ];            // attention out (fp16)
__device__ __align__(16) float  g_comb [M_ROWS * EMB];
__device__ __align__(16) float  g_x1   [M_ROWS * EMB];
__device__ __align__(16) __half g_qfh  [M_ROWS * NQ];            // ffn features (fp16)
__device__ __align__(16) float  g_ffn  [M_ROWS * EMB];
__device__ __align__(16) __half g_hh   [(size_t)M_ROWS * FFN];   // relu(qf@w1^T) fp16
__device__ __align__(16) __half g_wch  [EMB * NQ];               // w_combine fp16
__device__ __align__(16) __half g_w1h  [FFN * NQ];               // w_ffn1 fp16
__device__ __align__(16) __half g_w2h  [(size_t)EMB * FFN];      // w_ffn2 fp16

// ---------------- helpers ----------------
__device__ __forceinline__ uint32_t smem_u32(const void* p) {
    uint32_t a;
    asm("{ .reg .u64 t; cvta.to.shared.u64 t, %1; cvt.u32.u64 %0, t; }" : "=r"(a) : "l"(p));
    return a;
}
__device__ __forceinline__ void cp16(uint32_t dst, const void* src) {
    asm volatile("cp.async.cg.shared.global [%0], [%1], 16;" :: "r"(dst), "l"(src));
}
__device__ __forceinline__ void cp_commit() { asm volatile("cp.async.commit_group;" ::: "memory"); }
template <int N> __device__ __forceinline__ void cp_wait() {
    asm volatile("cp.async.wait_group %0;" :: "n"(N) : "memory");
}
__device__ __forceinline__ void mma_fp16(float* c, const uint32_t* a, const uint32_t* b) {
    asm volatile(
        "mma.sync.aligned.m16n8k16.row.col.f32.f16.f16.f32 "
        "{%0,%1,%2,%3}, {%4,%5,%6,%7}, {%8,%9}, {%0,%1,%2,%3};"
        : "+f"(c[0]), "+f"(c[1]), "+f"(c[2]), "+f"(c[3])
        : "r"(a[0]), "r"(a[1]), "r"(a[2]), "r"(a[3]), "r"(b[0]), "r"(b[1]));
}

static constexpr int SH = 40;            // smem row stride in halves (conflict-free bijection)

// load one 128-row x 32-half chunk into padded smem via cp.async (2 cp16/thread @256thr)
__device__ __forceinline__ void stage_chunk(uint32_t sdst, const __half* src,
                                            int row_stride_halves, int tid) {
    #pragma unroll
    for (int it = 0; it < 2; it++) {
        int idx = it * 256 + tid;               // 0..511
        int r = idx >> 2, u = idx & 3;
        cp16(sdst + (uint32_t)(r * SH * 2 + u * 16),
             src + (size_t)r * row_stride_halves + u * 8);
    }
}

// fragment compute over one K=32 chunk: warp tile 64x32, accum c[16][4]
__device__ __forceinline__ void compute_chunk(const __half* As, const __half* Bs,
                                              int wm, int wn, int g, int t,
                                              float c[16][4]) {
    #pragma unroll
    for (int ks = 0; ks < 2; ks++) {
        int tk = ks * 16;
        uint32_t af[4][4], bf[4][2];
        #pragma unroll
        for (int mf = 0; mf < 4; mf++) {
            const __half* ap = As + (wm + mf * 16 + g) * SH + tk + 2 * t;
            af[mf][0] = *(const uint32_t*)(ap);
            af[mf][1] = *(const uint32_t*)(ap + 8 * SH);
            af[mf][2] = *(const uint32_t*)(ap + 8);
            af[mf][3] = *(const uint32_t*)(ap + 8 * SH + 8);
        }
        #pragma unroll
        for (int nf = 0; nf < 4; nf++) {
            const __half* bp = Bs + (wn + nf * 8 + g) * SH + tk + 2 * t;
            bf[nf][0] = *(const uint32_t*)(bp);
            bf[nf][1] = *(const uint32_t*)(bp + 8);
        }
        #pragma unroll
        for (int mf = 0; mf < 4; mf++)
            #pragma unroll
            for (int nf = 0; nf < 4; nf++)
                mma_fp16(c[mf * 4 + nf], af[mf], bf[nf]);
    }
}

// block-wide sum of (s, q) over 256 threads; result broadcast
__device__ __forceinline__ void blockReduce2(float& s, float& q) {
    __shared__ float buf[16];
    #pragma unroll
    for (int o = 16; o > 0; o >>= 1) {
        s += __shfl_xor_sync(0xffffffffu, s, o);
        q += __shfl_xor_sync(0xffffffffu, q, o);
    }
    int w = threadIdx.x >> 5, l = threadIdx.x & 31;
    if (l == 0) { buf[w] = s; buf[8 + w] = q; }
    __syncthreads();
    if (threadIdx.x < 32) {
        float ss = (l < 8) ? buf[l] : 0.0f;
        float qq = (l < 8) ? buf[8 + l] : 0.0f;
        #pragma unroll
        for (int o = 4; o > 0; o >>= 1) {
            ss += __shfl_xor_sync(0xffffffffu, ss, o);
            qq += __shfl_xor_sync(0xffffffffu, qq, o);
        }
        if (l == 0) { buf[0] = ss; buf[8] = qq; }
    }
    __syncthreads();
    s = buf[0];
    q = buf[8];
}

// ---------------- fp32 -> fp16 conversion ----------------
__global__ __launch_bounds__(256) void conv_fp16(const float* __restrict__ src,
                                                 __half* __restrict__ dst) {
    size_t i = (size_t)blockIdx.x * 256 + threadIdx.x;   // float4 index
    float4 v = ((const float4*)src)[i];
    __half2 h0 = __floats2half2_rn(v.x, v.y);
    __half2 h1 = __floats2half2_rn(v.z, v.w);
    ((uint2*)dst)[i] = make_uint2(*(uint32_t*)&h0, *(uint32_t*)&h1);
}

// ---------------- attention ----------------
__global__ __launch_bounds__(256) void attn_kernel(const float* __restrict__ x,
                                                   const float* __restrict__ theta) {
    __shared__ float2 q2[1024];
    int bh = blockIdx.x;
    int b = bh >> 4, h = bh & 15;
    float c0 = cosf(theta[h * 2]);
    float c1 = cosf(theta[h * 2 + 1]);
    const float* xb = x + (size_t)b * 1024 * 1024 + h * 2;
    for (int i = threadIdx.x; i < 1024; i += 256) {
        float2 v = *(const float2*)(xb + (size_t)i * 1024);
        q2[i] = make_float2(c0 * cosf(v.x), c1 * cosf(v.y));
    }
    __syncthreads();
    int s = blockIdx.y * 256 + threadIdx.x;
    float2 qs = q2[s];
    const float inv_sqrt2 = 0.70710678118654752f;
    float sxp = qs.x * inv_sqrt2, syp = qs.y * inv_sqrt2;
    float sum = 0.0f, ax = 0.0f, ay = 0.0f;
    #pragma unroll 4
    for (int t = 0; t < 1024; t++) {
        float2 qt = q2[t];
        float e = __expf(sxp * qt.x + syp * qt.y);
        sum += e;
        ax += e * qt.x;
        ay += e * qt.y;
    }
    float inv = 1.0f / sum;
    size_t o = ((size_t)b * 1024 + s) * NQ + h * 2;
    __half2 hv = __floats2half2_rn(ax * inv, ay * inv);
    *(uint32_t*)&g_attnv[o] = *(uint32_t*)&hv;
}

// ---------------- tensor small-K GEMM (K=32, single chunk) ----------------
// mode 0: g_comb(fp32) = g_attnv @ g_wch^T ; mode 1: g_hh(fp16) = relu(g_qfh @ g_w1h^T)
__global__ __launch_bounds__(256, 2) void smallk_mma(int N, int mode) {
    __shared__ __align__(16) __half As[128 * SH];
    __shared__ __align__(16) __half Bs[128 * SH];
    const int tid = threadIdx.x;
    const int wid = tid >> 5, lane = tid & 31;
    const int g = lane >> 2, t = lane & 3;
    const int wm = (wid >> 2) * 64, wn = (wid & 3) * 32;
    const int m0 = blockIdx.y * 128, n0 = blockIdx.x * 128;
    const __half* A = (mode ? g_qfh : g_attnv) + (size_t)m0 * NQ;
    const __half* B = (mode ? g_w1h : g_wch) + (size_t)n0 * NQ;

    stage_chunk(smem_u32(As), A, NQ, tid);
    stage_chunk(smem_u32(Bs), B, NQ, tid);
    cp_commit();
    cp_wait<0>();
    __syncthreads();

    float c[16][4];
    #pragma unroll
    for (int i = 0; i < 16; i++)
        #pragma unroll
        for (int j = 0; j < 4; j++) c[i][j] = 0.0f;
    compute_chunk(As, Bs, wm, wn, g, t, c);

    #pragma unroll
    for (int mf = 0; mf < 4; mf++) {
        int r0 = m0 + wm + mf * 16 + g;
        #pragma unroll
        for (int nf = 0; nf < 4; nf++) {
            int col = n0 + wn + nf * 8 + 2 * t;
            float* cf = c[mf * 4 + nf];
            if (mode) {
                __half2 h0 = __floats2half2_rn(fmaxf(cf[0], 0.0f), fmaxf(cf[1], 0.0f));
                __half2 h1 = __floats2half2_rn(fmaxf(cf[2], 0.0f), fmaxf(cf[3], 0.0f));
                *(uint32_t*)&g_hh[(size_t)r0 * FFN + col]       = *(uint32_t*)&h0;
                *(uint32_t*)&g_hh[(size_t)(r0 + 8) * FFN + col] = *(uint32_t*)&h1;
            } else {
                *(float2*)&g_comb[(size_t)r0 * EMB + col]       = make_float2(cf[0], cf[1]);
                *(float2*)&g_comb[(size_t)(r0 + 8) * EMB + col] = make_float2(cf[2], cf[3]);
            }
        }
    }
}

// ---------------- LN1 + qf ----------------
__global__ __launch_bounds__(256) void ln1_kernel(const float* __restrict__ x,
                                                  const float* __restrict__ g1,
                                                  const float* __restrict__ b1,
                                                  const float* __restrict__ thf) {
    int row = blockIdx.x;
    const float* xr = x + (size_t)row * EMB;
    const float* cr = g_comb + (size_t)row * EMB;
    float v[4];
    float s = 0.0f, q = 0.0f;
    #pragma unroll
    for (int i = 0; i < 4; i++) {
        int e = i * 256 + threadIdx.x;
        v[i] = xr[e] + cr[e];
        s += v[i];
        q += v[i] * v[i];
    }
    blockReduce2(s, q);
    float mu = s * (1.0f / 1024.0f);
    float var = q * (1.0f / 1024.0f) - mu * mu;
    float rstd = rsqrtf(var + 1e-5f);
    #pragma unroll
    for (int i = 0; i < 4; i++) {
        int e = i * 256 + threadIdx.x;
        float y = (v[i] - mu) * rstd * g1[e] + b1[e];
        g_x1[(size_t)row * EMB + e] = y;
        if (i == 0 && threadIdx.x < NQ)
            g_qfh[(size_t)row * NQ + threadIdx.x] =
                __float2half(cosf(thf[threadIdx.x]) * cosf(y));
    }
}

// ---------------- big GEMM: fp16 mma, 3-stage cp.async pipeline ----------------
// g_ffn[8192,1024] = g_hh[8192,4096] @ g_w2h[1024,4096]^T
static constexpr int BK = 32;
static constexpr int NCH = FFN / BK;                  // 128
static constexpr int TILE_H = 128 * SH;               // halves per matrix tile
static constexpr int STAGE_H = 2 * TILE_H;            // A + B
static constexpr int BG_SMEM = 3 * STAGE_H * 2;       // bytes = 61440

__global__ __launch_bounds__(256, 2) void big_gemm_fp16() {
    extern __shared__ __align__(16) __half smem[];
    const int tid = threadIdx.x;
    const int wid = tid >> 5, lane = tid & 31;
    const int g = lane >> 2, t = lane & 3;
    const int wm = (wid >> 2) * 64, wn = (wid & 3) * 32;
    const int m0 = blockIdx.y * 128, n0 = blockIdx.x * 128;
    const uint32_t sbase = smem_u32(smem);

    const __half* Ag = g_hh  + (size_t)m0 * FFN;
    const __half* Bg = g_w2h + (size_t)n0 * FFN;

    float c[16][4];
    #pragma unroll
    for (int i = 0; i < 16; i++)
        #pragma unroll
        for (int j = 0; j < 4; j++) c[i][j] = 0.0f;

    auto load_chunk = [&](int ch, int stg) {
        uint32_t s0 = sbase + (uint32_t)stg * STAGE_H * 2;
        stage_chunk(s0,               Ag + ch * BK, FFN, tid);
        stage_chunk(s0 + TILE_H * 2,  Bg + ch * BK, FFN, tid);
        cp_commit();
    };

    load_chunk(0, 0);
    load_chunk(1, 1);
    for (int i = 0; i < NCH; i++) {
        if (i + 1 < NCH) cp_wait<1>();
        else             cp_wait<0>();
        __syncthreads();
        int stg = i % 3;
        const __half* As = smem + (size_t)stg * STAGE_H;
        const __half* Bs = As + TILE_H;
        compute_chunk(As, Bs, wm, wn, g, t, c);
        if (i + 2 < NCH) load_chunk(i + 2, (i + 2) % 3);
    }

    #pragma unroll
    for (int mf = 0; mf < 4; mf++) {
        int r0 = m0 + wm + mf * 16 + g;
        #pragma unroll
        for (int nf = 0; nf < 4; nf++) {
            int col = n0 + wn + nf * 8 + 2 * t;
            float* cf = c[mf * 4 + nf];
            *(float2*)&g_ffn[(size_t)r0 * EMB + col]       = make_float2(cf[0], cf[1]);
            *(float2*)&g_ffn[(size_t)(r0 + 8) * EMB + col] = make_float2(cf[2], cf[3]);
        }
    }
}

// ---------------- LN2 -> out ----------------
__global__ __launch_bounds__(256) void ln2_kernel(const float* __restrict__ g2,
                                                  const float* __restrict__ b2,
                                                  float* __restrict__ out) {
    int row = blockIdx.x;
    const float* xr = g_x1 + (size_t)row * EMB;
    const float* fr = g_ffn + (size_t)row * EMB;
    float v[4];
    float s = 0.0f, q = 0.0f;
    #pragma unroll
    for (int i = 0; i < 4; i++) {
        int e = i * 256 + threadIdx.x;
        v[i] = xr[e] + fr[e];
        s += v[i];
        q += v[i] * v[i];
    }
    blockReduce2(s, q);
    float mu = s * (1.0f / 1024.0f);
    float var = q * (1.0f / 1024.0f) - mu * mu;
    float rstd = rsqrtf(var + 1e-5f);
    #pragma unroll
    for (int i = 0; i < 4; i++) {
        int e = i * 256 + threadIdx.x;
        out[(size_t)row * EMB + e] = (v[i] - mu) * rstd * g2[e] + b2[e];
    }
}

// ---------------- launch ----------------
extern "C" void kernel_launch(void* const* d_in, const int* in_sizes, int n_in,
                              void* d_out, int out_size) {
    const float* x    = (const float*)d_in[0];
    const float* th_a = (const float*)d_in[1];
    const float* th_f = (const float*)d_in[2];
    const float* w_c  = (const float*)d_in[3];
    const float* w1   = (const float*)d_in[4];
    const float* w2   = (const float*)d_in[5];
    const float* g1   = (const float*)d_in[6];
    const float* b1   = (const float*)d_in[7];
    const float* g2   = (const float*)d_in[8];
    const float* b2   = (const float*)d_in[9];
    float* out = (float*)d_out;

    static bool attr_set = false;
    if (!attr_set) {
        cudaFuncSetAttribute(big_gemm_fp16, cudaFuncAttributeMaxDynamicSharedMemorySize, BG_SMEM);
        attr_set = true;
    }

    __half* wch; cudaGetSymbolAddress((void**)&wch, g_wch);
    __half* w1h; cudaGetSymbolAddress((void**)&w1h, g_w1h);
    __half* w2h; cudaGetSymbolAddress((void**)&w2h, g_w2h);

    conv_fp16<<<(EMB * NQ / 4) / 256 ? (EMB * NQ / 4) / 256 : 1, 256>>>(w_c, wch);
    conv_fp16<<<(FFN * NQ / 4) / 256, 256>>>(w1, w1h);
    conv_fp16<<<(EMB * FFN / 4) / 256, 256>>>(w2, w2h);
    attn_kernel<<<dim3(128, 4), 256>>>(x, th_a);
    smallk_mma<<<dim3(EMB / 128, M_ROWS / 128), 256>>>(EMB, 0);
    ln1_kernel<<<M_ROWS, 256>>>(x, g1, b1, th_f);
    smallk_mma<<<dim3(FFN / 128, M_ROWS / 128), 256>>>(FFN, 1);
    big_gemm_fp16<<<dim3(EMB / 128, M_ROWS / 128), 256, BG_SMEM>>>();
    ln2_kernel<<<M_ROWS, 256>>>(g2, b2, out);
}

// round 5
// speedup vs baseline: 5.7658x; 1.2091x over previous
#include <cuda_runtime.h>
#include <cuda_fp16.h>
#include <cstdint>

#define M_ROWS 8192
#define EMB 1024
#define FFN 4096
#define NQ 32

// ---------------- scratch (device globals; no allocations) ----------------
__device__ __align__(16) __half g_attnv[M_ROWS * NQ];            // attention out (fp16)
__device__ __align__(16) float  g_comb [M_ROWS * EMB];
__device__ __align__(16) float  g_x1   [M_ROWS * EMB];
__device__ __align__(16) __half g_qfh  [M_ROWS * NQ];            // ffn features (fp16)
__device__ __align__(16) float  g_ffn  [M_ROWS * EMB];
__device__ __align__(16) __half g_hh   [(size_t)M_ROWS * FFN];   // relu(qf@w1^T) fp16
__device__ __align__(16) __half g_wch  [EMB * NQ];
__device__ __align__(16) __half g_w1h  [FFN * NQ];
__device__ __align__(16) __half g_w2h  [(size_t)EMB * FFN];

// ---------------- helpers ----------------
__device__ __forceinline__ uint32_t smem_u32(const void* p) {
    uint32_t a;
    asm("{ .reg .u64 t; cvta.to.shared.u64 t, %1; cvt.u32.u64 %0, t; }" : "=r"(a) : "l"(p));
    return a;
}
__device__ __forceinline__ void cp16(uint32_t dst, const void* src) {
    asm volatile("cp.async.cg.shared.global [%0], [%1], 16;" :: "r"(dst), "l"(src));
}
__device__ __forceinline__ void cp_commit() { asm volatile("cp.async.commit_group;" ::: "memory"); }
template <int N> __device__ __forceinline__ void cp_wait() {
    asm volatile("cp.async.wait_group %0;" :: "n"(N) : "memory");
}
__device__ __forceinline__ void mma_fp16(float* c, const uint32_t* a, const uint32_t* b) {
    asm volatile(
        "mma.sync.aligned.m16n8k16.row.col.f32.f16.f16.f32 "
        "{%0,%1,%2,%3}, {%4,%5,%6,%7}, {%8,%9}, {%0,%1,%2,%3};"
        : "+f"(c[0]), "+f"(c[1]), "+f"(c[2]), "+f"(c[3])
        : "r"(a[0]), "r"(a[1]), "r"(a[2]), "r"(a[3]), "r"(b[0]), "r"(b[1]));
}
__device__ __forceinline__ void ldsm4(uint32_t* r, uint32_t addr) {
    asm volatile("ldmatrix.sync.aligned.m8n8.x4.shared.b16 {%0,%1,%2,%3}, [%4];"
                 : "=r"(r[0]), "=r"(r[1]), "=r"(r[2]), "=r"(r[3]) : "r"(addr));
}

static constexpr int SH = 40;            // smem row stride in halves (conflict-free)

// block-wide sum of (s, q) over 256 threads; result broadcast
__device__ __forceinline__ void blockReduce2(float& s, float& q) {
    __shared__ float buf[16];
    #pragma unroll
    for (int o = 16; o > 0; o >>= 1) {
        s += __shfl_xor_sync(0xffffffffu, s, o);
        q += __shfl_xor_sync(0xffffffffu, q, o);
    }
    int w = threadIdx.x >> 5, l = threadIdx.x & 31;
    if (l == 0) { buf[w] = s; buf[8 + w] = q; }
    __syncthreads();
    if (threadIdx.x < 32) {
        float ss = (l < 8) ? buf[l] : 0.0f;
        float qq = (l < 8) ? buf[8 + l] : 0.0f;
        #pragma unroll
        for (int o = 4; o > 0; o >>= 1) {
            ss += __shfl_xor_sync(0xffffffffu, ss, o);
            qq += __shfl_xor_sync(0xffffffffu, qq, o);
        }
        if (l == 0) { buf[0] = ss; buf[8] = qq; }
    }
    __syncthreads();
    s = buf[0];
    q = buf[8];
}

// ---------------- fp32 -> fp16 conversion ----------------
__global__ __launch_bounds__(256) void conv_fp16(const float* __restrict__ src,
                                                 __half* __restrict__ dst) {
    size_t i = (size_t)blockIdx.x * 256 + threadIdx.x;
    float4 v = ((const float4*)src)[i];
    __half2 h0 = __floats2half2_rn(v.x, v.y);
    __half2 h1 = __floats2half2_rn(v.z, v.w);
    ((uint2*)dst)[i] = make_uint2(*(uint32_t*)&h0, *(uint32_t*)&h1);
}

// ---------------- attention via separable Taylor features ----------------
// exp((qs.qt)/sqrt2) = (sum_i a^i/i!)(sum_j b^j/j!), a=qsx*qtx/sqrt2, b=qsy*qty/sqrt2.
// Truncate at degree 7 each (error ~3e-6). 64 features; factorials absorbed on t-side.
__global__ __launch_bounds__(256) void attn_kernel(const float* __restrict__ x,
                                                   const float* __restrict__ theta) {
    __shared__ float2 q2[1024];
    __shared__ float S[192];           // S0[64] | Sx[64] | Sy[64], idx [i*8+j]
    const float R = 0.84089641525371454f;   // 2^(-1/4)
    const float INVF[8]  = {1.f, 1.f, 0.5f, 1.f/6.f, 1.f/24.f, 1.f/120.f, 1.f/720.f, 1.f/5040.f};
    const float INVS[8]  = {1.f, 0.5f, 1.f/3.f, 0.25f, 0.2f, 1.f/6.f, 1.f/7.f, 0.125f};

    int bh = blockIdx.x;
    int b = bh >> 4, h = bh & 15;
    int tid = threadIdx.x;
    float c0 = cosf(theta[h * 2]);
    float c1 = cosf(theta[h * 2 + 1]);
    const float* xb = x + (size_t)b * 1024 * 1024 + h * 2;
    for (int i = tid; i < 1024; i += 256) {
        float2 v = *(const float2*)(xb + (size_t)i * 1024);
        q2[i] = make_float2(c0 * cosf(v.x), c1 * cosf(v.y));
    }
    __syncthreads();

    // phase 2: warp j accumulates features (i, j) for i=0..7
    {
        int j = tid >> 5, lane = tid & 31;
        float A0[8], Ax[8], Ay[8];
        #pragma unroll
        for (int i = 0; i < 8; i++) { A0[i] = 0.f; Ax[i] = 0.f; Ay[i] = 0.f; }
        for (int t = lane; t < 1024; t += 32) {
            float2 qt = q2[t];
            float utx = qt.x * R, uty = qt.y * R;
            float pty = INVF[j];
            for (int jj = 0; jj < j; jj++) pty *= uty;   // uniform per warp
            float p = pty;                               // i = 0
            #pragma unroll
            for (int i = 0; i < 8; i++) {
                A0[i] += p;
                Ax[i] = fmaf(p, qt.x, Ax[i]);
                Ay[i] = fmaf(p, qt.y, Ay[i]);
                p *= utx * INVS[i];                      // p_{i+1} = p_i * utx/(i+1)
            }
        }
        #pragma unroll
        for (int i = 0; i < 8; i++) {
            #pragma unroll
            for (int o = 16; o > 0; o >>= 1) {
                A0[i] += __shfl_xor_sync(0xffffffffu, A0[i], o);
                Ax[i] += __shfl_xor_sync(0xffffffffu, Ax[i], o);
                Ay[i] += __shfl_xor_sync(0xffffffffu, Ay[i], o);
            }
            if (lane == 0) {
                S[i * 8 + j]       = A0[i];
                S[64 + i * 8 + j]  = Ax[i];
                S[128 + i * 8 + j] = Ay[i];
            }
        }
    }
    __syncthreads();

    // phase 3: evaluate per s-row
    #pragma unroll
    for (int k = 0; k < 4; k++) {
        int s = k * 256 + tid;
        float2 qs = q2[s];
        float usx = qs.x * R, usy = qs.y * R;
        float psy[8];
        psy[0] = 1.f;
        #pragma unroll
        for (int j = 1; j < 8; j++) psy[j] = psy[j - 1] * usy;
        float d = 0.f, nx = 0.f, ny = 0.f, px = 1.f;
        #pragma unroll
        for (int i = 0; i < 8; i++) {
            float t0 = 0.f, t1 = 0.f, t2 = 0.f;
            #pragma unroll
            for (int j = 0; j < 8; j++) {
                float m = psy[j];
                t0 = fmaf(m, S[i * 8 + j], t0);
                t1 = fmaf(m, S[64 + i * 8 + j], t1);
                t2 = fmaf(m, S[128 + i * 8 + j], t2);
            }
            d  = fmaf(px, t0, d);
            nx = fmaf(px, t1, nx);
            ny = fmaf(px, t2, ny);
            px *= usx;
        }
        float inv = 1.0f / d;
        size_t o = ((size_t)b * 1024 + s) * NQ + h * 2;
        __half2 hv = __floats2half2_rn(nx * inv, ny * inv);
        *(uint32_t*)&g_attnv[o] = *(uint32_t*)&hv;
    }
}

// ---------------- tensor small-K GEMM (K=32, single chunk) ----------------
// mode 0: g_comb(fp32) = g_attnv @ g_wch^T ; mode 1: g_hh(fp16) = relu(g_qfh @ g_w1h^T)
__global__ __launch_bounds__(256, 2) void smallk_mma(int N, int mode) {
    __shared__ __align__(16) __half As[128 * SH];
    __shared__ __align__(16) __half Bs[128 * SH];
    const int tid = threadIdx.x;
    const int wid = tid >> 5, lane = tid & 31;
    const int g = lane >> 2, t = lane & 3;
    const int wm = (wid >> 2) * 64, wn = (wid & 3) * 32;
    const int m0 = blockIdx.y * 128, n0 = blockIdx.x * 128;
    const __half* A = (mode ? g_qfh : g_attnv) + (size_t)m0 * NQ;
    const __half* B = (mode ? g_w1h : g_wch) + (size_t)n0 * NQ;

    uint32_t sa = smem_u32(As), sb = smem_u32(Bs);
    #pragma unroll
    for (int it = 0; it < 2; it++) {
        int idx = it * 256 + tid;
        int r = idx >> 2, u = idx & 3;
        cp16(sa + (uint32_t)(r * SH * 2 + u * 16), A + (size_t)r * NQ + u * 8);
        cp16(sb + (uint32_t)(r * SH * 2 + u * 16), B + (size_t)r * NQ + u * 8);
    }
    cp_commit();
    cp_wait<0>();
    __syncthreads();

    float c[16][4];
    #pragma unroll
    for (int i = 0; i < 16; i++)
        #pragma unroll
        for (int j = 0; j < 4; j++) c[i][j] = 0.0f;

    #pragma unroll
    for (int ks = 0; ks < 2; ks++) {
        int tk = ks * 16;
        uint32_t af[4][4], bf[4][2];
        #pragma unroll
        for (int mf = 0; mf < 4; mf++) {
            const __half* ap = As + (wm + mf * 16 + g) * SH + tk + 2 * t;
            af[mf][0] = *(const uint32_t*)(ap);
            af[mf][1] = *(const uint32_t*)(ap + 8 * SH);
            af[mf][2] = *(const uint32_t*)(ap + 8);
            af[mf][3] = *(const uint32_t*)(ap + 8 * SH + 8);
        }
        #pragma unroll
        for (int nf = 0; nf < 4; nf++) {
            const __half* bp = Bs + (wn + nf * 8 + g) * SH + tk + 2 * t;
            bf[nf][0] = *(const uint32_t*)(bp);
            bf[nf][1] = *(const uint32_t*)(bp + 8);
        }
        #pragma unroll
        for (int mf = 0; mf < 4; mf++)
            #pragma unroll
            for (int nf = 0; nf < 4; nf++)
                mma_fp16(c[mf * 4 + nf], af[mf], bf[nf]);
    }

    #pragma unroll
    for (int mf = 0; mf < 4; mf++) {
        int r0 = m0 + wm + mf * 16 + g;
        #pragma unroll
        for (int nf = 0; nf < 4; nf++) {
            int col = n0 + wn + nf * 8 + 2 * t;
            float* cf = c[mf * 4 + nf];
            if (mode) {
                __half2 h0 = __floats2half2_rn(fmaxf(cf[0], 0.0f), fmaxf(cf[1], 0.0f));
                __half2 h1 = __floats2half2_rn(fmaxf(cf[2], 0.0f), fmaxf(cf[3], 0.0f));
                *(uint32_t*)&g_hh[(size_t)r0 * FFN + col]       = *(uint32_t*)&h0;
                *(uint32_t*)&g_hh[(size_t)(r0 + 8) * FFN + col] = *(uint32_t*)&h1;
            } else {
                *(float2*)&g_comb[(size_t)r0 * EMB + col]       = make_float2(cf[0], cf[1]);
                *(float2*)&g_comb[(size_t)(r0 + 8) * EMB + col] = make_float2(cf[2], cf[3]);
            }
        }
    }
}

// ---------------- LN1 + qf (float4) ----------------
__global__ __launch_bounds__(256) void ln1_kernel(const float* __restrict__ x,
                                                  const float* __restrict__ g1,
                                                  const float* __restrict__ b1,
                                                  const float* __restrict__ thf) {
    int row = blockIdx.x;
    int tid = threadIdx.x;
    float4 xv = ((const float4*)(x + (size_t)row * EMB))[tid];
    float4 cv = ((const float4*)(g_comb + (size_t)row * EMB))[tid];
    float4 v = make_float4(xv.x + cv.x, xv.y + cv.y, xv.z + cv.z, xv.w + cv.w);
    float s = v.x + v.y + v.z + v.w;
    float q = v.x * v.x + v.y * v.y + v.z * v.z + v.w * v.w;
    blockReduce2(s, q);
    float mu = s * (1.0f / 1024.0f);
    float var = q * (1.0f / 1024.0f) - mu * mu;
    float rstd = rsqrtf(var + 1e-5f);
    float4 gv = ((const float4*)g1)[tid];
    float4 bv = ((const float4*)b1)[tid];
    float4 y = make_float4((v.x - mu) * rstd * gv.x + bv.x,
                           (v.y - mu) * rstd * gv.y + bv.y,
                           (v.z - mu) * rstd * gv.z + bv.z,
                           (v.w - mu) * rstd * gv.w + bv.w);
    ((float4*)(g_x1 + (size_t)row * EMB))[tid] = y;
    if (tid < 8) {
        int e = tid * 4;
        __half2 h0 = __floats2half2_rn(cosf(thf[e + 0]) * cosf(y.x),
                                       cosf(thf[e + 1]) * cosf(y.y));
        __half2 h1 = __floats2half2_rn(cosf(thf[e + 2]) * cosf(y.z),
                                       cosf(thf[e + 3]) * cosf(y.w));
        *(uint2*)&g_qfh[(size_t)row * NQ + e] = make_uint2(*(uint32_t*)&h0, *(uint32_t*)&h1);
    }
}

// ---------------- big GEMM: fp16 mma, CTA 128x256, warp 64x64, ldmatrix ----------------
static constexpr int BK = 32;
static constexpr int NCH = FFN / BK;                  // 128
static constexpr int ATILE_B = 128 * SH * 2;          // 10240 bytes
static constexpr int BTILE_B = 256 * SH * 2;          // 20480 bytes
static constexpr int STAGE_B = ATILE_B + BTILE_B;     // 30720
static constexpr int BG_SMEM = 3 * STAGE_B;           // 92160

__global__ __launch_bounds__(256, 1) void big_gemm_fp16() {
    extern __shared__ __align__(16) __half smem[];
    const int tid = threadIdx.x;
    const int wid = tid >> 5, lane = tid & 31;
    const int g = lane >> 2, t = lane & 3;
    const int wm = (wid & 1) * 64, wn = (wid >> 1) * 64;
    const int m0 = blockIdx.y * 128, n0 = blockIdx.x * 256;
    const uint32_t sbase = smem_u32(smem);

    const __half* Ag = g_hh  + (size_t)m0 * FFN;
    const __half* Bg = g_w2h + (size_t)n0 * FFN;

    const int lrA = lane & 15, lcA = (lane >> 4) * 8;
    const int lrB = (lane & 7) + ((lane >> 4) << 3), lcB = ((lane >> 3) & 1) * 8;

    float c[32][4];
    #pragma unroll
    for (int i = 0; i < 32; i++)
        #pragma unroll
        for (int j = 0; j < 4; j++) c[i][j] = 0.0f;

    auto load_chunk = [&](int ch, int stg) {
        uint32_t s0 = sbase + (uint32_t)stg * STAGE_B;
        const __half* ag = Ag + ch * BK;
        #pragma unroll
        for (int it = 0; it < 2; it++) {
            int idx = it * 256 + tid;
            int r = idx >> 2, u = idx & 3;
            cp16(s0 + (uint32_t)(r * SH * 2 + u * 16), ag + (size_t)r * FFN + u * 8);
        }
        const __half* bg = Bg + ch * BK;
        uint32_t sB = s0 + ATILE_B;
        #pragma unroll
        for (int it = 0; it < 4; it++) {
            int idx = it * 256 + tid;
            int r = idx >> 2, u = idx & 3;
            cp16(sB + (uint32_t)(r * SH * 2 + u * 16), bg + (size_t)r * FFN + u * 8);
        }
        cp_commit();
    };

    load_chunk(0, 0);
    load_chunk(1, 1);
    for (int i = 0; i < NCH; i++) {
        if (i + 1 < NCH) cp_wait<1>();
        else             cp_wait<0>();
        __syncthreads();
        int stg = i % 3;
        uint32_t sA = sbase + (uint32_t)stg * STAGE_B;
        uint32_t sB = sA + ATILE_B;
        #pragma unroll
        for (int ks = 0; ks < 2; ks++) {
            int tk = ks * 16;
            uint32_t af[4][4], bf[8][2];
            #pragma unroll
            for (int mf = 0; mf < 4; mf++)
                ldsm4(af[mf], sA + (uint32_t)(((wm + mf * 16 + lrA) * SH + tk + lcA) * 2));
            #pragma unroll
            for (int nfp = 0; nfp < 4; nfp++) {
                uint32_t tmp[4];
                ldsm4(tmp, sB + (uint32_t)(((wn + nfp * 16 + lrB) * SH + tk + lcB) * 2));
                bf[2 * nfp][0]     = tmp[0];
                bf[2 * nfp][1]     = tmp[1];
                bf[2 * nfp + 1][0] = tmp[2];
                bf[2 * nfp + 1][1] = tmp[3];
            }
            #pragma unroll
            for (int mf = 0; mf < 4; mf++)
                #pragma unroll
                for (int nf = 0; nf < 8; nf++)
                    mma_fp16(c[mf * 8 + nf], af[mf], bf[nf]);
        }
        if (i + 2 < NCH) load_chunk(i + 2, (i + 2) % 3);
    }

    #pragma unroll
    for (int mf = 0; mf < 4; mf++) {
        int r0 = m0 + wm + mf * 16 + g;
        #pragma unroll
        for (int nf = 0; nf < 8; nf++) {
            int col = n0 + wn + nf * 8 + 2 * t;
            float* cf = c[mf * 8 + nf];
            *(float2*)&g_ffn[(size_t)r0 * EMB + col]       = make_float2(cf[0], cf[1]);
            *(float2*)&g_ffn[(size_t)(r0 + 8) * EMB + col] = make_float2(cf[2], cf[3]);
        }
    }
}

// ---------------- LN2 -> out (float4) ----------------
__global__ __launch_bounds__(256) void ln2_kernel(const float* __restrict__ g2,
                                                  const float* __restrict__ b2,
                                                  float* __restrict__ out) {
    int row = blockIdx.x;
    int tid = threadIdx.x;
    float4 xv = ((const float4*)(g_x1 + (size_t)row * EMB))[tid];
    float4 fv = ((const float4*)(g_ffn + (size_t)row * EMB))[tid];
    float4 v = make_float4(xv.x + fv.x, xv.y + fv.y, xv.z + fv.z, xv.w + fv.w);
    float s = v.x + v.y + v.z + v.w;
    float q = v.x * v.x + v.y * v.y + v.z * v.z + v.w * v.w;
    blockReduce2(s, q);
    float mu = s * (1.0f / 1024.0f);
    float var = q * (1.0f / 1024.0f) - mu * mu;
    float rstd = rsqrtf(var + 1e-5f);
    float4 gv = ((const float4*)g2)[tid];
    float4 bv = ((const float4*)b2)[tid];
    ((float4*)(out + (size_t)row * EMB))[tid] =
        make_float4((v.x - mu) * rstd * gv.x + bv.x,
                    (v.y - mu) * rstd * gv.y + bv.y,
                    (v.z - mu) * rstd * gv.z + bv.z,
                    (v.w - mu) * rstd * gv.w + bv.w);
}

// ---------------- launch ----------------
extern "C" void kernel_launch(void* const* d_in, const int* in_sizes, int n_in,
                              void* d_out, int out_size) {
    const float* x    = (const float*)d_in[0];
    const float* th_a = (const float*)d_in[1];
    const float* th_f = (const float*)d_in[2];
    const float* w_c  = (const float*)d_in[3];
    const float* w1   = (const float*)d_in[4];
    const float* w2   = (const float*)d_in[5];
    const float* g1   = (const float*)d_in[6];
    const float* b1   = (const float*)d_in[7];
    const float* g2   = (const float*)d_in[8];
    const float* b2   = (const float*)d_in[9];
    float* out = (float*)d_out;

    static bool attr_set = false;
    if (!attr_set) {
        cudaFuncSetAttribute(big_gemm_fp16, cudaFuncAttributeMaxDynamicSharedMemorySize, BG_SMEM);
        attr_set = true;
    }

    __half* wch; cudaGetSymbolAddress((void**)&wch, g_wch);
    __half* w1h; cudaGetSymbolAddress((void**)&w1h, g_w1h);
    __half* w2h; cudaGetSymbolAddress((void**)&w2h, g_w2h);

    conv_fp16<<<(EMB * NQ / 4) / 256 ? (EMB * NQ / 4) / 256 : 1, 256>>>(w_c, wch);
    conv_fp16<<<(FFN * NQ / 4) / 256, 256>>>(w1, w1h);
    conv_fp16<<<(EMB * FFN / 4) / 256, 256>>>(w2, w2h);
    attn_kernel<<<128, 256>>>(x, th_a);
    smallk_mma<<<dim3(EMB / 128, M_ROWS / 128), 256>>>(EMB, 0);
    ln1_kernel<<<M_ROWS, 256>>>(x, g1, b1, th_f);
    smallk_mma<<<dim3(FFN / 128, M_ROWS / 128), 256>>>(FFN, 1);
    big_gemm_fp16<<<dim3(EMB / 256, M_ROWS / 128), 256, BG_SMEM>>>();
    ln2_kernel<<<M_ROWS, 256>>>(g2, b2, out);
}

// round 6
// speedup vs baseline: 5.8797x; 1.0198x over previous
#include <cuda_runtime.h>
#include <cuda_fp16.h>
#include <cstdint>

#define M_ROWS 8192
#define EMB 1024
#define FFN 4096
#define NQ 32

// ---------------- scratch (device globals; no allocations) ----------------
__device__ __align__(16) __half g_attnv[M_ROWS * NQ];            // attention out (fp16)
__device__ __align__(16) float  g_comb [M_ROWS * EMB];
__device__ __align__(16) float  g_x1   [M_ROWS * EMB];
__device__ __align__(16) __half g_qfh  [M_ROWS * NQ];            // ffn features (fp16)
__device__ __align__(16) float  g_ffn  [M_ROWS * EMB];
__device__ __align__(16) __half g_wch  [EMB * NQ];
__device__ __align__(16) __half g_w1h  [FFN * NQ];
__device__ __align__(16) __half g_w2h  [(size_t)EMB * FFN];

// ---------------- helpers ----------------
__device__ __forceinline__ uint32_t smem_u32(const void* p) {
    uint32_t a;
    asm("{ .reg .u64 t; cvta.to.shared.u64 t, %1; cvt.u32.u64 %0, t; }" : "=r"(a) : "l"(p));
    return a;
}
__device__ __forceinline__ void cp16(uint32_t dst, const void* src) {
    asm volatile("cp.async.cg.shared.global [%0], [%1], 16;" :: "r"(dst), "l"(src));
}
__device__ __forceinline__ void cp_commit() { asm volatile("cp.async.commit_group;" ::: "memory"); }
template <int N> __device__ __forceinline__ void cp_wait() {
    asm volatile("cp.async.wait_group %0;" :: "n"(N) : "memory");
}
__device__ __forceinline__ void mma_fp16(float* c, const uint32_t* a, const uint32_t* b) {
    asm volatile(
        "mma.sync.aligned.m16n8k16.row.col.f32.f16.f16.f32 "
        "{%0,%1,%2,%3}, {%4,%5,%6,%7}, {%8,%9}, {%0,%1,%2,%3};"
        : "+f"(c[0]), "+f"(c[1]), "+f"(c[2]), "+f"(c[3])
        : "r"(a[0]), "r"(a[1]), "r"(a[2]), "r"(a[3]), "r"(b[0]), "r"(b[1]));
}
__device__ __forceinline__ void ldsm4(uint32_t* r, uint32_t addr) {
    asm volatile("ldmatrix.sync.aligned.m8n8.x4.shared.b16 {%0,%1,%2,%3}, [%4];"
                 : "=r"(r[0]), "=r"(r[1]), "=r"(r[2]), "=r"(r[3]) : "r"(addr));
}

static constexpr int SH = 40;            // smem row stride (halves) for k=32 tiles
static constexpr int SH2 = 72;           // smem row stride (halves) for k=64 tiles

// block-wide sum of (s, q) over 256 threads; result broadcast
__device__ __forceinline__ void blockReduce2(float& s, float& q) {
    __shared__ float buf[16];
    #pragma unroll
    for (int o = 16; o > 0; o >>= 1) {
        s += __shfl_xor_sync(0xffffffffu, s, o);
        q += __shfl_xor_sync(0xffffffffu, q, o);
    }
    int w = threadIdx.x >> 5, l = threadIdx.x & 31;
    if (l == 0) { buf[w] = s; buf[8 + w] = q; }
    __syncthreads();
    if (threadIdx.x < 32) {
        float ss = (l < 8) ? buf[l] : 0.0f;
        float qq = (l < 8) ? buf[8 + l] : 0.0f;
        #pragma unroll
        for (int o = 4; o > 0; o >>= 1) {
            ss += __shfl_xor_sync(0xffffffffu, ss, o);
            qq += __shfl_xor_sync(0xffffffffu, qq, o);
        }
        if (l == 0) { buf[0] = ss; buf[8] = qq; }
    }
    __syncthreads();
    s = buf[0];
    q = buf[8];
}

// ---------------- fp32 -> fp16 conversion ----------------
__global__ __launch_bounds__(256) void conv_fp16(const float* __restrict__ src,
                                                 __half* __restrict__ dst) {
    size_t i = (size_t)blockIdx.x * 256 + threadIdx.x;
    float4 v = ((const float4*)src)[i];
    __half2 h0 = __floats2half2_rn(v.x, v.y);
    __half2 h1 = __floats2half2_rn(v.z, v.w);
    ((uint2*)dst)[i] = make_uint2(*(uint32_t*)&h0, *(uint32_t*)&h1);
}

// ---------------- attention via separable Taylor features (512 thr) ----------------
__global__ __launch_bounds__(512) void attn_kernel(const float* __restrict__ x,
                                                   const float* __restrict__ theta) {
    __shared__ float2 q2[1024];
    __shared__ float S[192];           // S0[64] | Sx[64] | Sy[64], idx [i*8+j]
    const float R = 0.84089641525371454f;   // 2^(-1/4)
    const float INVF[8]  = {1.f, 1.f, 0.5f, 1.f/6.f, 1.f/24.f, 1.f/120.f, 1.f/720.f, 1.f/5040.f};
    const float INVS[8]  = {1.f, 0.5f, 1.f/3.f, 0.25f, 0.2f, 1.f/6.f, 1.f/7.f, 0.125f};

    int bh = blockIdx.x;
    int b = bh >> 4, h = bh & 15;
    int tid = threadIdx.x;
    float c0 = cosf(theta[h * 2]);
    float c1 = cosf(theta[h * 2 + 1]);
    const float* xb = x + (size_t)b * 1024 * 1024 + h * 2;
    #pragma unroll
    for (int i = 0; i < 2; i++) {
        int r = i * 512 + tid;
        float2 v = *(const float2*)(xb + (size_t)r * 1024);
        q2[r] = make_float2(c0 * cosf(v.x), c1 * cosf(v.y));
    }
    if (tid < 192) S[tid] = 0.0f;
    __syncthreads();

    // phase 2: 16 warps; warp w handles j = w&7 over half the t range
    {
        int wid = tid >> 5, lane = tid & 31;
        int j = wid & 7, half = wid >> 3;
        float A0[8], Ax[8], Ay[8];
        #pragma unroll
        for (int i = 0; i < 8; i++) { A0[i] = 0.f; Ax[i] = 0.f; Ay[i] = 0.f; }
        for (int t = half * 32 + lane; t < 1024; t += 64) {
            float2 qt = q2[t];
            float utx = qt.x * R, uty = qt.y * R;
            float pty = INVF[j];
            for (int jj = 0; jj < j; jj++) pty *= uty;
            float p = pty;
            #pragma unroll
            for (int i = 0; i < 8; i++) {
                A0[i] += p;
                Ax[i] = fmaf(p, qt.x, Ax[i]);
                Ay[i] = fmaf(p, qt.y, Ay[i]);
                p *= utx * INVS[i];
            }
        }
        #pragma unroll
        for (int i = 0; i < 8; i++) {
            #pragma unroll
            for (int o = 16; o > 0; o >>= 1) {
                A0[i] += __shfl_xor_sync(0xffffffffu, A0[i], o);
                Ax[i] += __shfl_xor_sync(0xffffffffu, Ax[i], o);
                Ay[i] += __shfl_xor_sync(0xffffffffu, Ay[i], o);
            }
            if (lane == 0) {
                atomicAdd(&S[i * 8 + j], A0[i]);
                atomicAdd(&S[64 + i * 8 + j], Ax[i]);
                atomicAdd(&S[128 + i * 8 + j], Ay[i]);
            }
        }
    }
    __syncthreads();

    // phase 3: evaluate per s-row
    #pragma unroll
    for (int k = 0; k < 2; k++) {
        int s = k * 512 + tid;
        float2 qs = q2[s];
        float usx = qs.x * R, usy = qs.y * R;
        float psy[8];
        psy[0] = 1.f;
        #pragma unroll
        for (int j = 1; j < 8; j++) psy[j] = psy[j - 1] * usy;
        float d = 0.f, nx = 0.f, ny = 0.f, px = 1.f;
        #pragma unroll
        for (int i = 0; i < 8; i++) {
            float t0 = 0.f, t1 = 0.f, t2 = 0.f;
            #pragma unroll
            for (int j = 0; j < 8; j++) {
                float m = psy[j];
                t0 = fmaf(m, S[i * 8 + j], t0);
                t1 = fmaf(m, S[64 + i * 8 + j], t1);
                t2 = fmaf(m, S[128 + i * 8 + j], t2);
            }
            d  = fmaf(px, t0, d);
            nx = fmaf(px, t1, nx);
            ny = fmaf(px, t2, ny);
            px *= usx;
        }
        float inv = 1.0f / d;
        size_t o = ((size_t)b * 1024 + s) * NQ + h * 2;
        __half2 hv = __floats2half2_rn(nx * inv, ny * inv);
        *(uint32_t*)&g_attnv[o] = *(uint32_t*)&hv;
    }
}

// ---------------- combine GEMM (K=32): g_comb = g_attnv @ g_wch^T ----------------
__global__ __launch_bounds__(256, 2) void combine_mma() {
    __shared__ __align__(16) __half As[128 * SH];
    __shared__ __align__(16) __half Bs[128 * SH];
    const int tid = threadIdx.x;
    const int wid = tid >> 5, lane = tid & 31;
    const int g = lane >> 2, t = lane & 3;
    const int wm = (wid >> 2) * 64, wn = (wid & 3) * 32;
    const int m0 = blockIdx.y * 128, n0 = blockIdx.x * 128;
    const __half* A = g_attnv + (size_t)m0 * NQ;
    const __half* B = g_wch + (size_t)n0 * NQ;

    uint32_t sa = smem_u32(As), sb = smem_u32(Bs);
    #pragma unroll
    for (int it = 0; it < 2; it++) {
        int idx = it * 256 + tid;
        int r = idx >> 2, u = idx & 3;
        cp16(sa + (uint32_t)(r * SH * 2 + u * 16), A + (size_t)r * NQ + u * 8);
        cp16(sb + (uint32_t)(r * SH * 2 + u * 16), B + (size_t)r * NQ + u * 8);
    }
    cp_commit();
    cp_wait<0>();
    __syncthreads();

    float c[16][4];
    #pragma unroll
    for (int i = 0; i < 16; i++)
        #pragma unroll
        for (int j = 0; j < 4; j++) c[i][j] = 0.0f;

    #pragma unroll
    for (int ks = 0; ks < 2; ks++) {
        int tk = ks * 16;
        uint32_t af[4][4], bf[4][2];
        #pragma unroll
        for (int mf = 0; mf < 4; mf++) {
            const __half* ap = As + (wm + mf * 16 + g) * SH + tk + 2 * t;
            af[mf][0] = *(const uint32_t*)(ap);
            af[mf][1] = *(const uint32_t*)(ap + 8 * SH);
            af[mf][2] = *(const uint32_t*)(ap + 8);
            af[mf][3] = *(const uint32_t*)(ap + 8 * SH + 8);
        }
        #pragma unroll
        for (int nf = 0; nf < 4; nf++) {
            const __half* bp = Bs + (wn + nf * 8 + g) * SH + tk + 2 * t;
            bf[nf][0] = *(const uint32_t*)(bp);
            bf[nf][1] = *(const uint32_t*)(bp + 8);
        }
        #pragma unroll
        for (int mf = 0; mf < 4; mf++)
            #pragma unroll
            for (int nf = 0; nf < 4; nf++)
                mma_fp16(c[mf * 4 + nf], af[mf], bf[nf]);
    }

    #pragma unroll
    for (int mf = 0; mf < 4; mf++) {
        int r0 = m0 + wm + mf * 16 + g;
        #pragma unroll
        for (int nf = 0; nf < 4; nf++) {
            int col = n0 + wn + nf * 8 + 2 * t;
            float* cf = c[mf * 4 + nf];
            *(float2*)&g_comb[(size_t)r0 * EMB + col]       = make_float2(cf[0], cf[1]);
            *(float2*)&g_comb[(size_t)(r0 + 8) * EMB + col] = make_float2(cf[2], cf[3]);
        }
    }
}

// ---------------- LN1 + qf (float4) ----------------
__global__ __launch_bounds__(256) void ln1_kernel(const float* __restrict__ x,
                                                  const float* __restrict__ g1,
                                                  const float* __restrict__ b1,
                                                  const float* __restrict__ thf) {
    int row = blockIdx.x;
    int tid = threadIdx.x;
    float4 xv = ((const float4*)(x + (size_t)row * EMB))[tid];
    float4 cv = ((const float4*)(g_comb + (size_t)row * EMB))[tid];
    float4 v = make_float4(xv.x + cv.x, xv.y + cv.y, xv.z + cv.z, xv.w + cv.w);
    float s = v.x + v.y + v.z + v.w;
    float q = v.x * v.x + v.y * v.y + v.z * v.z + v.w * v.w;
    blockReduce2(s, q);
    float mu = s * (1.0f / 1024.0f);
    float var = q * (1.0f / 1024.0f) - mu * mu;
    float rstd = rsqrtf(var + 1e-5f);
    float4 gv = ((const float4*)g1)[tid];
    float4 bv = ((const float4*)b1)[tid];
    float4 y = make_float4((v.x - mu) * rstd * gv.x + bv.x,
                           (v.y - mu) * rstd * gv.y + bv.y,
                           (v.z - mu) * rstd * gv.z + bv.z,
                           (v.w - mu) * rstd * gv.w + bv.w);
    ((float4*)(g_x1 + (size_t)row * EMB))[tid] = y;
    if (tid < 8) {
        int e = tid * 4;
        __half2 h0 = __floats2half2_rn(cosf(thf[e + 0]) * cosf(y.x),
                                       cosf(thf[e + 1]) * cosf(y.y));
        __half2 h1 = __floats2half2_rn(cosf(thf[e + 2]) * cosf(y.z),
                                       cosf(thf[e + 3]) * cosf(y.w));
        *(uint2*)&g_qfh[(size_t)row * NQ + e] = make_uint2(*(uint32_t*)&h0, *(uint32_t*)&h1);
    }
}

// ---------------- fused FFN: g_ffn = relu(qf@W1^T) @ W2^T ----------------
// CTA tile M=128 x N=256; K-chunk BK=64 FFN cols; h-chunk computed in-kernel.
static constexpr int BK = 64;
static constexpr int NCH = FFN / BK;                  // 64
static constexpr int QF_B   = 128 * SH * 2;           // 10240
static constexpr int W1ST_B = 64 * SH * 2;            // 5120 per stage
static constexpr int W2ST_B = 256 * SH2 * 2;          // 36864 per stage
static constexpr int HB_B   = 128 * SH2 * 2;          // 18432 per buffer
static constexpr int OFF_W1 = QF_B;                   // 10240
static constexpr int OFF_W2 = OFF_W1 + 3 * W1ST_B;    // 25600
static constexpr int OFF_HB = OFF_W2 + 3 * W2ST_B;    // 136192
static constexpr int FG_SMEM = OFF_HB + 2 * HB_B;     // 173056

__global__ __launch_bounds__(256, 1) void ffn_fused() {
    extern __shared__ __align__(16) __half smem[];
    const int tid = threadIdx.x;
    const int wid = tid >> 5, lane = tid & 31;
    const int g = lane >> 2, t = lane & 3;
    const int wm = (wid & 1) * 64, wn = (wid >> 1) * 64;
    const int m0 = blockIdx.y * 128, n0 = blockIdx.x * 256;
    const uint32_t sbase = smem_u32(smem);
    const uint32_t sqf = sbase, shb = sbase + OFF_HB;

    const int lrA = lane & 15, lcA = (lane >> 4) * 8;
    const int lrB = (lane & 7) + ((lane >> 4) << 3), lcB = ((lane >> 3) & 1) * 8;

    float c[32][4];
    #pragma unroll
    for (int i = 0; i < 32; i++)
        #pragma unroll
        for (int j = 0; j < 4; j++) c[i][j] = 0.0f;

    auto load_stage = [&](int ch, int stg) {
        uint32_t w1a = sbase + OFF_W1 + (uint32_t)stg * W1ST_B;
        {   // W1 chunk: 64 rows x 32 halves
            int r = tid >> 2, u = tid & 3;
            cp16(w1a + (uint32_t)(r * SH * 2 + u * 16),
                 g_w1h + (size_t)(ch * BK + r) * NQ + u * 8);
        }
        uint32_t w2a = sbase + OFF_W2 + (uint32_t)stg * W2ST_B;
        const __half* bg = g_w2h + (size_t)n0 * FFN + ch * BK;
        #pragma unroll
        for (int it = 0; it < 8; it++) {   // W2 chunk: 256 rows x 64 halves
            int idx = it * 256 + tid;
            int r = idx >> 3, u = idx & 7;
            cp16(w2a + (uint32_t)(r * SH2 * 2 + u * 16), bg + (size_t)r * FFN + u * 8);
        }
        cp_commit();
    };

    // qf tile (128 x 32) + stages 0,1
    {
        const __half* A = g_qfh + (size_t)m0 * NQ;
        #pragma unroll
        for (int it = 0; it < 2; it++) {
            int idx = it * 256 + tid;
            int r = idx >> 2, u = idx & 3;
            cp16(sqf + (uint32_t)(r * SH * 2 + u * 16), A + (size_t)r * NQ + u * 8);
        }
        cp_commit();
        load_stage(0, 0);
        load_stage(1, 1);
    }

    for (int i = 0; i < NCH; i++) {
        if (i + 1 < NCH) cp_wait<1>();
        else             cp_wait<0>();
        __syncthreads();
        int stg = i % 3;
        uint32_t w1a = sbase + OFF_W1 + (uint32_t)stg * W1ST_B;
        uint32_t w2a = sbase + OFF_W2 + (uint32_t)stg * W2ST_B;
        uint32_t hb  = shb + (uint32_t)(i & 1) * HB_B;

        // ---- MMA1: h[128,64] = relu(qf @ W1chunk^T); warp wid does rows 16*wid..+15
        {
            float c1[8][4];
            #pragma unroll
            for (int a = 0; a < 8; a++)
                #pragma unroll
                for (int bq = 0; bq < 4; bq++) c1[a][bq] = 0.0f;
            #pragma unroll
            for (int ks = 0; ks < 2; ks++) {
                int tk = ks * 16;
                uint32_t af[4], bf[8][2];
                ldsm4(af, sqf + (uint32_t)(((wid * 16 + lrA) * SH + tk + lcA) * 2));
                #pragma unroll
                for (int nfp = 0; nfp < 4; nfp++) {
                    uint32_t tmp[4];
                    ldsm4(tmp, w1a + (uint32_t)(((nfp * 16 + lrB) * SH + tk + lcB) * 2));
                    bf[2 * nfp][0] = tmp[0]; bf[2 * nfp][1] = tmp[1];
                    bf[2 * nfp + 1][0] = tmp[2]; bf[2 * nfp + 1][1] = tmp[3];
                }
                #pragma unroll
                for (int nf = 0; nf < 8; nf++)
                    mma_fp16(c1[nf], af, bf[nf]);
            }
            // relu + cvt + store to hbuf
            int r0 = wid * 16 + g;
            #pragma unroll
            for (int nf = 0; nf < 8; nf++) {
                int col = nf * 8 + 2 * t;
                __half2 h0 = __floats2half2_rn(fmaxf(c1[nf][0], 0.f), fmaxf(c1[nf][1], 0.f));
                __half2 h1 = __floats2half2_rn(fmaxf(c1[nf][2], 0.f), fmaxf(c1[nf][3], 0.f));
                *(uint32_t*)(smem + ((shb - sbase) / 2) + (i & 1) * (HB_B / 2) + r0 * SH2 + col) =
                    *(uint32_t*)&h0;
                *(uint32_t*)(smem + ((shb - sbase) / 2) + (i & 1) * (HB_B / 2) + (r0 + 8) * SH2 + col) =
                    *(uint32_t*)&h1;
            }
        }
        __syncthreads();

        // ---- MMA2: accumulate h @ W2chunk^T
        #pragma unroll
        for (int ks = 0; ks < 4; ks++) {
            int tk = ks * 16;
            uint32_t af[4][4], bf[8][2];
            #pragma unroll
            for (int mf = 0; mf < 4; mf++)
                ldsm4(af[mf], hb + (uint32_t)(((wm + mf * 16 + lrA) * SH2 + tk + lcA) * 2));
            #pragma unroll
            for (int nfp = 0; nfp < 4; nfp++) {
                uint32_t tmp[4];
                ldsm4(tmp, w2a + (uint32_t)(((wn + nfp * 16 + lrB) * SH2 + tk + lcB) * 2));
                bf[2 * nfp][0] = tmp[0]; bf[2 * nfp][1] = tmp[1];
                bf[2 * nfp + 1][0] = tmp[2]; bf[2 * nfp + 1][1] = tmp[3];
            }
            #pragma unroll
            for (int mf = 0; mf < 4; mf++)
                #pragma unroll
                for (int nf = 0; nf < 8; nf++)
                    mma_fp16(c[mf * 8 + nf], af[mf], bf[nf]);
        }
        if (i + 2 < NCH) load_stage(i + 2, (i + 2) % 3);
    }

    #pragma unroll
    for (int mf = 0; mf < 4; mf++) {
        int r0 = m0 + wm + mf * 16 + g;
        #pragma unroll
        for (int nf = 0; nf < 8; nf++) {
            int col = n0 + wn + nf * 8 + 2 * t;
            float* cf = c[mf * 8 + nf];
            *(float2*)&g_ffn[(size_t)r0 * EMB + col]       = make_float2(cf[0], cf[1]);
            *(float2*)&g_ffn[(size_t)(r0 + 8) * EMB + col] = make_float2(cf[2], cf[3]);
        }
    }
}

// ---------------- LN2 -> out (float4) ----------------
__global__ __launch_bounds__(256) void ln2_kernel(const float* __restrict__ g2,
                                                  const float* __restrict__ b2,
                                                  float* __restrict__ out) {
    int row = blockIdx.x;
    int tid = threadIdx.x;
    float4 xv = ((const float4*)(g_x1 + (size_t)row * EMB))[tid];
    float4 fv = ((const float4*)(g_ffn + (size_t)row * EMB))[tid];
    float4 v = make_float4(xv.x + fv.x, xv.y + fv.y, xv.z + fv.z, xv.w + fv.w);
    float s = v.x + v.y + v.z + v.w;
    float q = v.x * v.x + v.y * v.y + v.z * v.z + v.w * v.w;
    blockReduce2(s, q);
    float mu = s * (1.0f / 1024.0f);
    float var = q * (1.0f / 1024.0f) - mu * mu;
    float rstd = rsqrtf(var + 1e-5f);
    float4 gv = ((const float4*)g2)[tid];
    float4 bv = ((const float4*)b2)[tid];
    ((float4*)(out + (size_t)row * EMB))[tid] =
        make_float4((v.x - mu) * rstd * gv.x + bv.x,
                    (v.y - mu) * rstd * gv.y + bv.y,
                    (v.z - mu) * rstd * gv.z + bv.z,
                    (v.w - mu) * rstd * gv.w + bv.w);
}

// ---------------- launch ----------------
extern "C" void kernel_launch(void* const* d_in, const int* in_sizes, int n_in,
                              void* d_out, int out_size) {
    const float* x    = (const float*)d_in[0];
    const float* th_a = (const float*)d_in[1];
    const float* th_f = (const float*)d_in[2];
    const float* w_c  = (const float*)d_in[3];
    const float* w1   = (const float*)d_in[4];
    const float* w2   = (const float*)d_in[5];
    const float* g1   = (const float*)d_in[6];
    const float* b1   = (const float*)d_in[7];
    const float* g2   = (const float*)d_in[8];
    const float* b2   = (const float*)d_in[9];
    float* out = (float*)d_out;

    static bool attr_set = false;
    if (!attr_set) {
        cudaFuncSetAttribute(ffn_fused, cudaFuncAttributeMaxDynamicSharedMemorySize, FG_SMEM);
        attr_set = true;
    }

    __half* wch; cudaGetSymbolAddress((void**)&wch, g_wch);
    __half* w1h; cudaGetSymbolAddress((void**)&w1h, g_w1h);
    __half* w2h; cudaGetSymbolAddress((void**)&w2h, g_w2h);

    conv_fp16<<<32, 256>>>(w_c, wch);
    conv_fp16<<<128, 256>>>(w1, w1h);
    conv_fp16<<<(EMB * FFN / 4) / 256, 256>>>(w2, w2h);
    attn_kernel<<<128, 512>>>(x, th_a);
    combine_mma<<<dim3(EMB / 128, M_ROWS / 128), 256>>>();
    ln1_kernel<<<M_ROWS, 256>>>(x, g1, b1, th_f);
    ffn_fused<<<dim3(EMB / 256, M_ROWS / 128), 256, FG_SMEM>>>();
    ln2_kernel<<<M_ROWS, 256>>>(g2, b2, out);
}

// round 7
// speedup vs baseline: 6.5295x; 1.1105x over previous
#include <cuda_runtime.h>
#include <cuda_fp16.h>
#include <cstdint>

#define M_ROWS 8192
#define EMB 1024
#define FFN 4096
#define NQ 32

// ---------------- scratch (device globals; no allocations) ----------------
__device__ __align__(16) __half g_attnv[M_ROWS * NQ];            // attention out (fp16)
__device__ __align__(16) __half g_combh[M_ROWS * EMB];           // combine out (fp16)
__device__ __align__(16) float  g_x1   [M_ROWS * EMB];
__device__ __align__(16) __half g_qfh  [M_ROWS * NQ];            // ffn features (fp16)
__device__ __align__(16) __half g_ffnh [M_ROWS * EMB];           // ffn out (fp16)
__device__ __align__(16) __half g_wch  [EMB * NQ];
__device__ __align__(16) __half g_w1h  [FFN * NQ];
__device__ __align__(16) __half g_w2h  [(size_t)EMB * FFN];

// ---------------- helpers ----------------
__device__ __forceinline__ uint32_t smem_u32(const void* p) {
    uint32_t a;
    asm("{ .reg .u64 t; cvta.to.shared.u64 t, %1; cvt.u32.u64 %0, t; }" : "=r"(a) : "l"(p));
    return a;
}
__device__ __forceinline__ void cp16(uint32_t dst, const void* src) {
    asm volatile("cp.async.cg.shared.global [%0], [%1], 16;" :: "r"(dst), "l"(src));
}
__device__ __forceinline__ void cp_commit() { asm volatile("cp.async.commit_group;" ::: "memory"); }
template <int N> __device__ __forceinline__ void cp_wait() {
    asm volatile("cp.async.wait_group %0;" :: "n"(N) : "memory");
}
__device__ __forceinline__ void mma_fp16(float* c, const uint32_t* a, const uint32_t* b) {
    asm volatile(
        "mma.sync.aligned.m16n8k16.row.col.f32.f16.f16.f32 "
        "{%0,%1,%2,%3}, {%4,%5,%6,%7}, {%8,%9}, {%0,%1,%2,%3};"
        : "+f"(c[0]), "+f"(c[1]), "+f"(c[2]), "+f"(c[3])
        : "r"(a[0]), "r"(a[1]), "r"(a[2]), "r"(a[3]), "r"(b[0]), "r"(b[1]));
}
__device__ __forceinline__ void ldsm4(uint32_t* r, uint32_t addr) {
    asm volatile("ldmatrix.sync.aligned.m8n8.x4.shared.b16 {%0,%1,%2,%3}, [%4];"
                 : "=r"(r[0]), "=r"(r[1]), "=r"(r[2]), "=r"(r[3]) : "r"(addr));
}

static constexpr int SH = 40;            // smem row stride (halves) for k=32 tiles
static constexpr int SH2 = 72;           // smem row stride (halves) for k=64 tiles

// block-wide sum of (s, q) over 256 threads; result broadcast
__device__ __forceinline__ void blockReduce2(float& s, float& q) {
    __shared__ float buf[16];
    #pragma unroll
    for (int o = 16; o > 0; o >>= 1) {
        s += __shfl_xor_sync(0xffffffffu, s, o);
        q += __shfl_xor_sync(0xffffffffu, q, o);
    }
    int w = threadIdx.x >> 5, l = threadIdx.x & 31;
    if (l == 0) { buf[w] = s; buf[8 + w] = q; }
    __syncthreads();
    if (threadIdx.x < 32) {
        float ss = (l < 8) ? buf[l] : 0.0f;
        float qq = (l < 8) ? buf[8 + l] : 0.0f;
        #pragma unroll
        for (int o = 4; o > 0; o >>= 1) {
            ss += __shfl_xor_sync(0xffffffffu, ss, o);
            qq += __shfl_xor_sync(0xffffffffu, qq, o);
        }
        if (l == 0) { buf[0] = ss; buf[8] = qq; }
    }
    __syncthreads();
    s = buf[0];
    q = buf[8];
}

// ---------------- fp32 -> fp16 conversion ----------------
__global__ __launch_bounds__(256) void conv_fp16(const float* __restrict__ src,
                                                 __half* __restrict__ dst) {
    size_t i = (size_t)blockIdx.x * 256 + threadIdx.x;
    float4 v = ((const float4*)src)[i];
    __half2 h0 = __floats2half2_rn(v.x, v.y);
    __half2 h1 = __floats2half2_rn(v.z, v.w);
    ((uint2*)dst)[i] = make_uint2(*(uint32_t*)&h0, *(uint32_t*)&h1);
}

// ---------------- attention via separable Taylor features (R5 version, 256 thr) ----------------
__global__ __launch_bounds__(256) void attn_kernel(const float* __restrict__ x,
                                                   const float* __restrict__ theta) {
    __shared__ float2 q2[1024];
    __shared__ float S[192];           // S0[64] | Sx[64] | Sy[64], idx [i*8+j]
    const float R = 0.84089641525371454f;   // 2^(-1/4)
    const float INVF[8]  = {1.f, 1.f, 0.5f, 1.f/6.f, 1.f/24.f, 1.f/120.f, 1.f/720.f, 1.f/5040.f};
    const float INVS[8]  = {1.f, 0.5f, 1.f/3.f, 0.25f, 0.2f, 1.f/6.f, 1.f/7.f, 0.125f};

    int bh = blockIdx.x;
    int b = bh >> 4, h = bh & 15;
    int tid = threadIdx.x;
    float c0 = cosf(theta[h * 2]);
    float c1 = cosf(theta[h * 2 + 1]);
    const float* xb = x + (size_t)b * 1024 * 1024 + h * 2;
    for (int i = tid; i < 1024; i += 256) {
        float2 v = *(const float2*)(xb + (size_t)i * 1024);
        q2[i] = make_float2(c0 * cosf(v.x), c1 * cosf(v.y));
    }
    __syncthreads();

    // phase 2: warp j accumulates features (i, j) for i=0..7
    {
        int j = tid >> 5, lane = tid & 31;
        float A0[8], Ax[8], Ay[8];
        #pragma unroll
        for (int i = 0; i < 8; i++) { A0[i] = 0.f; Ax[i] = 0.f; Ay[i] = 0.f; }
        for (int t = lane; t < 1024; t += 32) {
            float2 qt = q2[t];
            float utx = qt.x * R, uty = qt.y * R;
            float pty = INVF[j];
            for (int jj = 0; jj < j; jj++) pty *= uty;   // uniform per warp
            float p = pty;
            #pragma unroll
            for (int i = 0; i < 8; i++) {
                A0[i] += p;
                Ax[i] = fmaf(p, qt.x, Ax[i]);
                Ay[i] = fmaf(p, qt.y, Ay[i]);
                p *= utx * INVS[i];
            }
        }
        #pragma unroll
        for (int i = 0; i < 8; i++) {
            #pragma unroll
            for (int o = 16; o > 0; o >>= 1) {
                A0[i] += __shfl_xor_sync(0xffffffffu, A0[i], o);
                Ax[i] += __shfl_xor_sync(0xffffffffu, Ax[i], o);
                Ay[i] += __shfl_xor_sync(0xffffffffu, Ay[i], o);
            }
            if (lane == 0) {
                S[i * 8 + j]       = A0[i];
                S[64 + i * 8 + j]  = Ax[i];
                S[128 + i * 8 + j] = Ay[i];
            }
        }
    }
    __syncthreads();

    // phase 3: evaluate per s-row
    #pragma unroll
    for (int k = 0; k < 4; k++) {
        int s = k * 256 + tid;
        float2 qs = q2[s];
        float usx = qs.x * R, usy = qs.y * R;
        float psy[8];
        psy[0] = 1.f;
        #pragma unroll
        for (int j = 1; j < 8; j++) psy[j] = psy[j - 1] * usy;
        float d = 0.f, nx = 0.f, ny = 0.f, px = 1.f;
        #pragma unroll
        for (int i = 0; i < 8; i++) {
            float t0 = 0.f, t1 = 0.f, t2 = 0.f;
            #pragma unroll
            for (int j = 0; j < 8; j++) {
                float m = psy[j];
                t0 = fmaf(m, S[i * 8 + j], t0);
                t1 = fmaf(m, S[64 + i * 8 + j], t1);
                t2 = fmaf(m, S[128 + i * 8 + j], t2);
            }
            d  = fmaf(px, t0, d);
            nx = fmaf(px, t1, nx);
            ny = fmaf(px, t2, ny);
            px *= usx;
        }
        float inv = 1.0f / d;
        size_t o = ((size_t)b * 1024 + s) * NQ + h * 2;
        __half2 hv = __floats2half2_rn(nx * inv, ny * inv);
        *(uint32_t*)&g_attnv[o] = *(uint32_t*)&hv;
    }
}

// ---------------- combine GEMM (K=32): g_combh = g_attnv @ g_wch^T (fp16 out) ----------------
__global__ __launch_bounds__(256, 2) void combine_mma() {
    __shared__ __align__(16) __half As[128 * SH];
    __shared__ __align__(16) __half Bs[128 * SH];
    const int tid = threadIdx.x;
    const int wid = tid >> 5, lane = tid & 31;
    const int g = lane >> 2, t = lane & 3;
    const int wm = (wid >> 2) * 64, wn = (wid & 3) * 32;
    const int m0 = blockIdx.y * 128, n0 = blockIdx.x * 128;
    const __half* A = g_attnv + (size_t)m0 * NQ;
    const __half* B = g_wch + (size_t)n0 * NQ;

    uint32_t sa = smem_u32(As), sb = smem_u32(Bs);
    #pragma unroll
    for (int it = 0; it < 2; it++) {
        int idx = it * 256 + tid;
        int r = idx >> 2, u = idx & 3;
        cp16(sa + (uint32_t)(r * SH * 2 + u * 16), A + (size_t)r * NQ + u * 8);
        cp16(sb + (uint32_t)(r * SH * 2 + u * 16), B + (size_t)r * NQ + u * 8);
    }
    cp_commit();
    cp_wait<0>();
    __syncthreads();

    float c[16][4];
    #pragma unroll
    for (int i = 0; i < 16; i++)
        #pragma unroll
        for (int j = 0; j < 4; j++) c[i][j] = 0.0f;

    #pragma unroll
    for (int ks = 0; ks < 2; ks++) {
        int tk = ks * 16;
        uint32_t af[4][4], bf[4][2];
        #pragma unroll
        for (int mf = 0; mf < 4; mf++) {
            const __half* ap = As + (wm + mf * 16 + g) * SH + tk + 2 * t;
            af[mf][0] = *(const uint32_t*)(ap);
            af[mf][1] = *(const uint32_t*)(ap + 8 * SH);
            af[mf][2] = *(const uint32_t*)(ap + 8);
            af[mf][3] = *(const uint32_t*)(ap + 8 * SH + 8);
        }
        #pragma unroll
        for (int nf = 0; nf < 4; nf++) {
            const __half* bp = Bs + (wn + nf * 8 + g) * SH + tk + 2 * t;
            bf[nf][0] = *(const uint32_t*)(bp);
            bf[nf][1] = *(const uint32_t*)(bp + 8);
        }
        #pragma unroll
        for (int mf = 0; mf < 4; mf++)
            #pragma unroll
            for (int nf = 0; nf < 4; nf++)
                mma_fp16(c[mf * 4 + nf], af[mf], bf[nf]);
    }

    #pragma unroll
    for (int mf = 0; mf < 4; mf++) {
        int r0 = m0 + wm + mf * 16 + g;
        #pragma unroll
        for (int nf = 0; nf < 4; nf++) {
            int col = n0 + wn + nf * 8 + 2 * t;
            float* cf = c[mf * 4 + nf];
            __half2 h0 = __floats2half2_rn(cf[0], cf[1]);
            __half2 h1 = __floats2half2_rn(cf[2], cf[3]);
            *(uint32_t*)&g_combh[(size_t)r0 * EMB + col]       = *(uint32_t*)&h0;
            *(uint32_t*)&g_combh[(size_t)(r0 + 8) * EMB + col] = *(uint32_t*)&h1;
        }
    }
}

// ---------------- LN1 + qf (float4 / half2) ----------------
__global__ __launch_bounds__(256) void ln1_kernel(const float* __restrict__ x,
                                                  const float* __restrict__ g1,
                                                  const float* __restrict__ b1,
                                                  const float* __restrict__ thf) {
    int row = blockIdx.x;
    int tid = threadIdx.x;
    float4 xv = ((const float4*)(x + (size_t)row * EMB))[tid];
    uint2 cu = ((const uint2*)(g_combh + (size_t)row * EMB))[tid];
    float2 c01 = __half22float2(*(__half2*)&cu.x);
    float2 c23 = __half22float2(*(__half2*)&cu.y);
    float4 v = make_float4(xv.x + c01.x, xv.y + c01.y, xv.z + c23.x, xv.w + c23.y);
    float s = v.x + v.y + v.z + v.w;
    float q = v.x * v.x + v.y * v.y + v.z * v.z + v.w * v.w;
    blockReduce2(s, q);
    float mu = s * (1.0f / 1024.0f);
    float var = q * (1.0f / 1024.0f) - mu * mu;
    float rstd = rsqrtf(var + 1e-5f);
    float4 gv = ((const float4*)g1)[tid];
    float4 bv = ((const float4*)b1)[tid];
    float4 y = make_float4((v.x - mu) * rstd * gv.x + bv.x,
                           (v.y - mu) * rstd * gv.y + bv.y,
                           (v.z - mu) * rstd * gv.z + bv.z,
                           (v.w - mu) * rstd * gv.w + bv.w);
    ((float4*)(g_x1 + (size_t)row * EMB))[tid] = y;
    if (tid < 8) {
        int e = tid * 4;
        __half2 h0 = __floats2half2_rn(cosf(thf[e + 0]) * cosf(y.x),
                                       cosf(thf[e + 1]) * cosf(y.y));
        __half2 h1 = __floats2half2_rn(cosf(thf[e + 2]) * cosf(y.z),
                                       cosf(thf[e + 3]) * cosf(y.w));
        *(uint2*)&g_qfh[(size_t)row * NQ + e] = make_uint2(*(uint32_t*)&h0, *(uint32_t*)&h1);
    }
}

// ---------------- fused FFN: g_ffnh = relu(qf@W1^T) @ W2^T (512 thr) ----------------
static constexpr int BK = 64;
static constexpr int NCH = FFN / BK;                  // 64
static constexpr int QF_B   = 128 * SH * 2;           // 10240
static constexpr int W1ST_B = 64 * SH * 2;            // 5120 per stage
static constexpr int W2ST_B = 256 * SH2 * 2;          // 36864 per stage
static constexpr int HB_B   = 128 * SH2 * 2;          // 18432 per buffer
static constexpr int OFF_W1 = QF_B;                   // 10240
static constexpr int OFF_W2 = OFF_W1 + 3 * W1ST_B;    // 25600
static constexpr int OFF_HB = OFF_W2 + 3 * W2ST_B;    // 136192
static constexpr int FG_SMEM = OFF_HB + 2 * HB_B;     // 173056

__global__ __launch_bounds__(512, 1) void ffn_fused() {
    extern __shared__ __align__(16) __half smem[];
    const int tid = threadIdx.x;
    const int wid = tid >> 5, lane = tid & 31;
    const int g = lane >> 2, t = lane & 3;
    const int m0 = blockIdx.y * 128, n0 = blockIdx.x * 256;
    const uint32_t sbase = smem_u32(smem);
    const uint32_t sqf = sbase, shb = sbase + OFF_HB;

    const int lrA = lane & 15, lcA = (lane >> 4) * 8;
    const int lrB = (lane & 7) + ((lane >> 4) << 3), lcB = ((lane >> 3) & 1) * 8;

    // MMA1 warp mapping: 16 warps, warp tile 16(M) x 32(N of h)
    const int m1 = (wid & 7) * 16, n1 = (wid >> 3) * 32;
    // MMA2 warp mapping: 4x4 grid, warp tile 32(M) x 64(N)
    const int wm2 = (wid & 3) * 32, wn2 = (wid >> 2) * 64;

    float c[16][4];
    #pragma unroll
    for (int i = 0; i < 16; i++)
        #pragma unroll
        for (int j = 0; j < 4; j++) c[i][j] = 0.0f;

    auto load_stage = [&](int ch, int stg) {
        uint32_t w1a = sbase + OFF_W1 + (uint32_t)stg * W1ST_B;
        if (tid < 256) {   // W1 chunk: 64 rows x 32 halves = 256 cp16
            int r = tid >> 2, u = tid & 3;
            cp16(w1a + (uint32_t)(r * SH * 2 + u * 16),
                 g_w1h + (size_t)(ch * BK + r) * NQ + u * 8);
        }
        uint32_t w2a = sbase + OFF_W2 + (uint32_t)stg * W2ST_B;
        const __half* bg = g_w2h + (size_t)n0 * FFN + ch * BK;
        #pragma unroll
        for (int it = 0; it < 4; it++) {   // W2 chunk: 256 rows x 64 halves = 2048 cp16
            int idx = it * 512 + tid;
            int r = idx >> 3, u = idx & 7;
            cp16(w2a + (uint32_t)(r * SH2 * 2 + u * 16), bg + (size_t)r * FFN + u * 8);
        }
        cp_commit();
    };

    // qf tile (128 x 32) + stages 0,1
    {
        const __half* A = g_qfh + (size_t)m0 * NQ;
        int r = tid >> 2, u = tid & 3;        // 512 cp16 exactly
        cp16(sqf + (uint32_t)(r * SH * 2 + u * 16), A + (size_t)r * NQ + u * 8);
        cp_commit();
        load_stage(0, 0);
        load_stage(1, 1);
    }

    for (int i = 0; i < NCH; i++) {
        if (i + 1 < NCH) cp_wait<1>();
        else             cp_wait<0>();
        __syncthreads();
        int stg = i % 3;
        uint32_t w1a = sbase + OFF_W1 + (uint32_t)stg * W1ST_B;
        uint32_t w2a = sbase + OFF_W2 + (uint32_t)stg * W2ST_B;
        uint32_t hb  = shb + (uint32_t)(i & 1) * HB_B;

        // ---- MMA1: h[128,64] = relu(qf @ W1chunk^T); warp tile 16x32
        {
            float c1[4][4];
            #pragma unroll
            for (int a = 0; a < 4; a++)
                #pragma unroll
                for (int bq = 0; bq < 4; bq++) c1[a][bq] = 0.0f;
            #pragma unroll
            for (int ks = 0; ks < 2; ks++) {
                int tk = ks * 16;
                uint32_t af[4], bf[4][2];
                ldsm4(af, sqf + (uint32_t)(((m1 + lrA) * SH + tk + lcA) * 2));
                #pragma unroll
                for (int nfp = 0; nfp < 2; nfp++) {
                    uint32_t tmp[4];
                    ldsm4(tmp, w1a + (uint32_t)(((n1 + nfp * 16 + lrB) * SH + tk + lcB) * 2));
                    bf[2 * nfp][0] = tmp[0]; bf[2 * nfp][1] = tmp[1];
                    bf[2 * nfp + 1][0] = tmp[2]; bf[2 * nfp + 1][1] = tmp[3];
                }
                #pragma unroll
                for (int nf = 0; nf < 4; nf++)
                    mma_fp16(c1[nf], af, bf[nf]);
            }
            int r0 = m1 + g;
            #pragma unroll
            for (int nf = 0; nf < 4; nf++) {
                int col = n1 + nf * 8 + 2 * t;
                __half2 h0 = __floats2half2_rn(fmaxf(c1[nf][0], 0.f), fmaxf(c1[nf][1], 0.f));
                __half2 h1 = __floats2half2_rn(fmaxf(c1[nf][2], 0.f), fmaxf(c1[nf][3], 0.f));
                asm volatile("st.shared.b32 [%0], %1;" ::
                    "r"(hb + (uint32_t)((r0 * SH2 + col) * 2)), "r"(*(uint32_t*)&h0) : "memory");
                asm volatile("st.shared.b32 [%0], %1;" ::
                    "r"(hb + (uint32_t)(((r0 + 8) * SH2 + col) * 2)), "r"(*(uint32_t*)&h1) : "memory");
            }
        }
        __syncthreads();

        // ---- MMA2: accumulate h @ W2chunk^T; warp tile 32x64
        #pragma unroll
        for (int ks = 0; ks < 4; ks++) {
            int tk = ks * 16;
            uint32_t af[2][4], bf[8][2];
            #pragma unroll
            for (int mf = 0; mf < 2; mf++)
                ldsm4(af[mf], hb + (uint32_t)(((wm2 + mf * 16 + lrA) * SH2 + tk + lcA) * 2));
            #pragma unroll
            for (int nfp = 0; nfp < 4; nfp++) {
                uint32_t tmp[4];
                ldsm4(tmp, w2a + (uint32_t)(((wn2 + nfp * 16 + lrB) * SH2 + tk + lcB) * 2));
                bf[2 * nfp][0] = tmp[0]; bf[2 * nfp][1] = tmp[1];
                bf[2 * nfp + 1][0] = tmp[2]; bf[2 * nfp + 1][1] = tmp[3];
            }
            #pragma unroll
            for (int mf = 0; mf < 2; mf++)
                #pragma unroll
                for (int nf = 0; nf < 8; nf++)
                    mma_fp16(c[mf * 8 + nf], af[mf], bf[nf]);
        }
        if (i + 2 < NCH) load_stage(i + 2, (i + 2) % 3);
    }

    #pragma unroll
    for (int mf = 0; mf < 2; mf++) {
        int r0 = m0 + wm2 + mf * 16 + g;
        #pragma unroll
        for (int nf = 0; nf < 8; nf++) {
            int col = n0 + wn2 + nf * 8 + 2 * t;
            float* cf = c[mf * 8 + nf];
            __half2 h0 = __floats2half2_rn(cf[0], cf[1]);
            __half2 h1 = __floats2half2_rn(cf[2], cf[3]);
            *(uint32_t*)&g_ffnh[(size_t)r0 * EMB + col]       = *(uint32_t*)&h0;
            *(uint32_t*)&g_ffnh[(size_t)(r0 + 8) * EMB + col] = *(uint32_t*)&h1;
        }
    }
}

// ---------------- LN2 -> out (float4 / half2) ----------------
__global__ __launch_bounds__(256) void ln2_kernel(const float* __restrict__ g2,
                                                  const float* __restrict__ b2,
                                                  float* __restrict__ out) {
    int row = blockIdx.x;
    int tid = threadIdx.x;
    float4 xv = ((const float4*)(g_x1 + (size_t)row * EMB))[tid];
    uint2 fu = ((const uint2*)(g_ffnh + (size_t)row * EMB))[tid];
    float2 f01 = __half22float2(*(__half2*)&fu.x);
    float2 f23 = __half22float2(*(__half2*)&fu.y);
    float4 v = make_float4(xv.x + f01.x, xv.y + f01.y, xv.z + f23.x, xv.w + f23.y);
    float s = v.x + v.y + v.z + v.w;
    float q = v.x * v.x + v.y * v.y + v.z * v.z + v.w * v.w;
    blockReduce2(s, q);
    float mu = s * (1.0f / 1024.0f);
    float var = q * (1.0f / 1024.0f) - mu * mu;
    float rstd = rsqrtf(var + 1e-5f);
    float4 gv = ((const float4*)g2)[tid];
    float4 bv = ((const float4*)b2)[tid];
    ((float4*)(out + (size_t)row * EMB))[tid] =
        make_float4((v.x - mu) * rstd * gv.x + bv.x,
                    (v.y - mu) * rstd * gv.y + bv.y,
                    (v.z - mu) * rstd * gv.z + bv.z,
                    (v.w - mu) * rstd * gv.w + bv.w);
}

// ---------------- launch ----------------
extern "C" void kernel_launch(void* const* d_in, const int* in_sizes, int n_in,
                              void* d_out, int out_size) {
    const float* x    = (const float*)d_in[0];
    const float* th_a = (const float*)d_in[1];
    const float* th_f = (const float*)d_in[2];
    const float* w_c  = (const float*)d_in[3];
    const float* w1   = (const float*)d_in[4];
    const float* w2   = (const float*)d_in[5];
    const float* g1   = (const float*)d_in[6];
    const float* b1   = (const float*)d_in[7];
    const float* g2   = (const float*)d_in[8];
    const float* b2   = (const float*)d_in[9];
    float* out = (float*)d_out;

    static bool attr_set = false;
    if (!attr_set) {
        cudaFuncSetAttribute(ffn_fused, cudaFuncAttributeMaxDynamicSharedMemorySize, FG_SMEM);
        attr_set = true;
    }

    __half* wch; cudaGetSymbolAddress((void**)&wch, g_wch);
    __half* w1h; cudaGetSymbolAddress((void**)&w1h, g_w1h);
    __half* w2h; cudaGetSymbolAddress((void**)&w2h, g_w2h);

    conv_fp16<<<32, 256>>>(w_c, wch);
    conv_fp16<<<128, 256>>>(w1, w1h);
    conv_fp16<<<(EMB * FFN / 4) / 256, 256>>>(w2, w2h);
    attn_kernel<<<128, 256>>>(x, th_a);
    combine_mma<<<dim3(EMB / 128, M_ROWS / 128), 256>>>();
    ln1_kernel<<<M_ROWS, 256>>>(x, g1, b1, th_f);
    ffn_fused<<<dim3(EMB / 256, M_ROWS / 128), 512, FG_SMEM>>>();
    ln2_kernel<<<M_ROWS, 256>>>(g2, b2, out);
}